// round 10
// baseline (speedup 1.0000x reference)
#include <cuda_runtime.h>
#include <cuda_bf16.h>
#include <cstdint>

#define BGR   128          // graphs
#define EPG   4096         // edges per graph
#define ETOT  (BGR*EPG)    // 524288 edges
#define FDIM  128
#define NTMAX (BGR*512)    // 65536 max nodes

// ---------------- device scratch ----------------
__device__ __nv_bfloat16 g_Xa_hi[NTMAX*FDIM];   // aggregated input, split bf16
__device__ __nv_bfloat16 g_Xa_lo[NTMAX*FDIM];
__device__ __nv_bfloat16 g_Wt_hi[FDIM*FDIM];    // W transposed [n][k], split bf16
__device__ __nv_bfloat16 g_Wt_lo[FDIM*FDIM];
__device__ float g_bufB[NTMAX*FDIM];   // H  (post-GEMM features)
__device__ float g_bufC[NTMAX*FDIM];   // xnew (next-stage input)
__device__ float g_s0   [NTMAX];
__device__ int   g_src[ETOT];
__device__ int   g_dst[ETOT];
__device__ unsigned short g_csr_src16[ETOT];    // local src ids (u16)
__device__ float g_csr_w [ETOT];
__device__ int   g_cnt   [NTMAX];
__device__ int   g_off   [NTMAX];
__device__ int   g_newidx[NTMAX];

// =====================================================================
// k_prep: per-graph prep (remap+mask+count+dinv+warp-scan+CSR fill).
// 1024 threads/block; extra block (b == BGR) converts W.
// =====================================================================
template<int NPG, int REMAP, int WRITEBACK>
__global__ __launch_bounds__(1024)
void k_prep(const int* __restrict__ esrc, const int* __restrict__ edst,
            const int* __restrict__ newidx,
            int* __restrict__ osrc, int* __restrict__ odst,
            int* __restrict__ cnt_g, int* __restrict__ off_g,
            unsigned short* __restrict__ csr_src_g, float* __restrict__ csr_w_g,
            const float* __restrict__ W,
            __nv_bfloat16* __restrict__ Wt_hi, __nv_bfloat16* __restrict__ Wt_lo) {
    const int b = blockIdx.x, t = threadIdx.x;
    if (b == BGR) {
        // transpose + split W[128k][128n] -> Wt[n][k]
#pragma unroll
        for (int it = 0; it < 16; it++) {
            int idx = t + it*1024;
            int n = idx >> 7, k = idx & 127;
            float v = W[k*128 + n];
            __nv_bfloat16 h = __float2bfloat16(v);
            Wt_hi[idx] = h;
            Wt_lo[idx] = __float2bfloat16(v - __bfloat162float(h));
        }
        return;
    }
    __shared__ int   s_cnt [NPG];
    __shared__ int   s_cur [NPG];
    __shared__ float s_dinv[NPG];
    __shared__ int   s_ws  [NPG/32];        // warp partial sums
    const int ebase = b * EPG;
    const int nbase = b * NPG;
    const int lane = t & 31, wid = t >> 5;
    if (t < NPG) s_cnt[t] = 0;
    __syncthreads();

    int ls[4], ldst[4];
#pragma unroll
    for (int u = 0; u < 4; u++) {
        int e = ebase + u*1024 + t;
        int s = esrc[e], d = edst[e];
        if (REMAP) {
            if (d >= 0) {
                int ns = newidx[s], nd = newidx[d];
                if (ns < 0 || nd < 0) d = -1;
                else { s = ns; d = nd; }
            }
        }
        if (WRITEBACK) { osrc[e] = s; odst[e] = d; }
        if (d >= 0) {
            ls[u]   = s - nbase;
            ldst[u] = d - nbase;
            atomicAdd(&s_cnt[ldst[u]], 1);
        } else ldst[u] = -1;
    }
    __syncthreads();

    // ---- two-level warp-shuffle exclusive scan over NPG counts ----
    int c = 0, vincl = 0;
    if (t < NPG) {
        c = s_cnt[t];
        vincl = c;
#pragma unroll
        for (int d = 1; d < 32; d <<= 1) {
            int nv = __shfl_up_sync(0xFFFFFFFFu, vincl, d);
            if (lane >= d) vincl += nv;
        }
        if (lane == 31) s_ws[wid] = vincl;
        cnt_g[nbase + t] = c;
        s_dinv[t] = rsqrtf((float)c + 1.f);
    }
    __syncthreads();
    if (t < 32) {
        constexpr int NW = NPG/32;
        int v = (t < NW) ? s_ws[t] : 0;
#pragma unroll
        for (int d = 1; d < 32; d <<= 1) {
            int nv = __shfl_up_sync(0xFFFFFFFFu, v, d);
            if (lane >= d) v += nv;
        }
        if (t < NW) s_ws[t] = v;        // inclusive warp-sum prefix
    }
    __syncthreads();
    if (t < NPG) {
        int base = (wid > 0) ? s_ws[wid - 1] : 0;
        int excl = base + vincl - c;
        off_g[nbase + t] = ebase + excl;
        s_cur[t]  = excl;
    }
    __syncthreads();

#pragma unroll
    for (int u = 0; u < 4; u++) {
        if (ldst[u] >= 0) {
            int pos = atomicAdd(&s_cur[ldst[u]], 1);
            csr_src_g[ebase + pos] = (unsigned short)ls[u];
            csr_w_g  [ebase + pos] = s_dinv[ls[u]] * s_dinv[ldst[u]];
        }
    }
}

// =====================================================================
// k_agg: high-occupancy aggregation, one warp per node (MLP=4),
//        output written as split bf16 for the tensor-core GEMM.
// =====================================================================
__global__ __launch_bounds__(256)
void k_agg(const float* __restrict__ X, const int* __restrict__ cnt,
           const int* __restrict__ off,
           const unsigned short* __restrict__ csr_src,
           const float* __restrict__ csr_w,
           __nv_bfloat16* __restrict__ Xa_hi, __nv_bfloat16* __restrict__ Xa_lo,
           int nt, int npgShift) {
    int warp = (blockIdx.x*256 + threadIdx.x) >> 5;
    int lane = threadIdx.x & 31;
    if (warp >= nt) return;
    int i = warp;
    int nbase = (i >> npgShift) << npgShift;
    int c = cnt[i], o = off[i];
    float self = 1.f / ((float)c + 1.f);
    size_t gi = (size_t)i*128 + lane*4;
    float4 hv = *(const float4*)(X + gi);
    float4 a0 = make_float4(self*hv.x, self*hv.y, self*hv.z, self*hv.w);
    float4 a1 = make_float4(0,0,0,0), a2 = make_float4(0,0,0,0), a3 = make_float4(0,0,0,0);
    int j = 0;
    for (; j + 4 <= c; j += 4) {
        int   n0 = csr_src[o+j],   n1 = csr_src[o+j+1];
        int   n2 = csr_src[o+j+2], n3 = csr_src[o+j+3];
        float w0 = csr_w[o+j],   w1 = csr_w[o+j+1];
        float w2 = csr_w[o+j+2], w3 = csr_w[o+j+3];
        float4 h0 = *(const float4*)(X + (size_t)(nbase+n0)*128 + lane*4);
        float4 h1 = *(const float4*)(X + (size_t)(nbase+n1)*128 + lane*4);
        float4 h2 = *(const float4*)(X + (size_t)(nbase+n2)*128 + lane*4);
        float4 h3 = *(const float4*)(X + (size_t)(nbase+n3)*128 + lane*4);
        a0.x += w0*h0.x; a0.y += w0*h0.y; a0.z += w0*h0.z; a0.w += w0*h0.w;
        a1.x += w1*h1.x; a1.y += w1*h1.y; a1.z += w1*h1.z; a1.w += w1*h1.w;
        a2.x += w2*h2.x; a2.y += w2*h2.y; a2.z += w2*h2.z; a2.w += w2*h2.w;
        a3.x += w3*h3.x; a3.y += w3*h3.y; a3.z += w3*h3.z; a3.w += w3*h3.w;
    }
    for (; j < c; j++) {
        int s = csr_src[o+j]; float w = csr_w[o+j];
        float4 hs = *(const float4*)(X + (size_t)(nbase+s)*128 + lane*4);
        a0.x += w*hs.x; a0.y += w*hs.y; a0.z += w*hs.z; a0.w += w*hs.w;
    }
    a0.x += a1.x + a2.x + a3.x;
    a0.y += a1.y + a2.y + a3.y;
    a0.z += a1.z + a2.z + a3.z;
    a0.w += a1.w + a2.w + a3.w;
    float f[4] = {a0.x, a0.y, a0.z, a0.w};
    __nv_bfloat16 hi4[4], lo4[4];
#pragma unroll
    for (int e = 0; e < 4; e++) {
        hi4[e] = __float2bfloat16(f[e]);
        lo4[e] = __float2bfloat16(f[e] - __bfloat162float(hi4[e]));
    }
    *(uint2*)(Xa_hi + gi) = *(uint2*)hi4;
    *(uint2*)(Xa_lo + gi) = *(uint2*)lo4;
}

// =====================================================================
// Tensor-core GEMM (split-bf16 operands preconverted; 3 MMA terms):
//   H[M,128] = relu(Xa @ W + b); epilogue also computes s0 = H.Ws
// =====================================================================
__device__ __forceinline__ void mma_bf16(float* d, const unsigned* a, const unsigned* b) {
    asm volatile(
        "mma.sync.aligned.m16n8k16.row.col.f32.bf16.bf16.f32 "
        "{%0,%1,%2,%3}, {%4,%5,%6,%7}, {%8,%9}, {%0,%1,%2,%3};\n"
        : "+f"(d[0]), "+f"(d[1]), "+f"(d[2]), "+f"(d[3])
        : "r"(a[0]), "r"(a[1]), "r"(a[2]), "r"(a[3]), "r"(b[0]), "r"(b[1]));
}

__global__ __launch_bounds__(256)
void k_gemm_tc(const __nv_bfloat16* __restrict__ A_hi,
               const __nv_bfloat16* __restrict__ A_lo,
               const __nv_bfloat16* __restrict__ Wt_hi,
               const __nv_bfloat16* __restrict__ Wt_lo,
               const float* __restrict__ bias, const float* __restrict__ Ws,
               float* __restrict__ C, float* __restrict__ s0) {
    __shared__ __align__(16) __nv_bfloat16 As_hi[128][40];
    __shared__ __align__(16) __nv_bfloat16 As_lo[128][40];
    __shared__ __align__(16) __nv_bfloat16 Bt_hi[128][40];
    __shared__ __align__(16) __nv_bfloat16 Bt_lo[128][40];
    __shared__ float s0part[2][128];

    const int t = threadIdx.x;
    const int warp = t >> 5, lane = t & 31;
    const int warpM = warp >> 1, warpN = warp & 1;
    const int row0 = blockIdx.x * 128;
    const int lq = lane >> 2;
    const int lr = lane & 3;

    float acc[2][8][4];
#pragma unroll
    for (int mt = 0; mt < 2; mt++)
#pragma unroll
        for (int nt = 0; nt < 8; nt++)
#pragma unroll
            for (int r = 0; r < 4; r++) acc[mt][nt][r] = 0.f;

    for (int kc = 0; kc < 4; kc++) {
#pragma unroll
        for (int it = 0; it < 2; it++) {
            int idx = t + it*256;
            int row = idx >> 2;
            int kq  = (idx & 3) * 8;
            size_t ga = (size_t)(row0 + row)*128 + kc*32 + kq;
            *(uint4*)&As_hi[row][kq] = *(const uint4*)(A_hi + ga);
            *(uint4*)&As_lo[row][kq] = *(const uint4*)(A_lo + ga);
            size_t gb = (size_t)row*128 + kc*32 + kq;
            *(uint4*)&Bt_hi[row][kq] = *(const uint4*)(Wt_hi + gb);
            *(uint4*)&Bt_lo[row][kq] = *(const uint4*)(Wt_lo + gb);
        }
        __syncthreads();

#pragma unroll
        for (int ks = 0; ks < 2; ks++) {
            const int kb = ks * 16;
            unsigned a_hi[2][4], a_lo[2][4], b_hi[8][2], b_lo[8][2];
#pragma unroll
            for (int mt = 0; mt < 2; mt++) {
                int m = warpM*32 + mt*16 + lq;
                a_hi[mt][0] = *(const unsigned*)&As_hi[m    ][kb + 2*lr];
                a_hi[mt][1] = *(const unsigned*)&As_hi[m + 8][kb + 2*lr];
                a_hi[mt][2] = *(const unsigned*)&As_hi[m    ][kb + 2*lr + 8];
                a_hi[mt][3] = *(const unsigned*)&As_hi[m + 8][kb + 2*lr + 8];
                a_lo[mt][0] = *(const unsigned*)&As_lo[m    ][kb + 2*lr];
                a_lo[mt][1] = *(const unsigned*)&As_lo[m + 8][kb + 2*lr];
                a_lo[mt][2] = *(const unsigned*)&As_lo[m    ][kb + 2*lr + 8];
                a_lo[mt][3] = *(const unsigned*)&As_lo[m + 8][kb + 2*lr + 8];
            }
#pragma unroll
            for (int nt = 0; nt < 8; nt++) {
                int n = warpN*64 + nt*8 + lq;
                b_hi[nt][0] = *(const unsigned*)&Bt_hi[n][kb + 2*lr];
                b_hi[nt][1] = *(const unsigned*)&Bt_hi[n][kb + 2*lr + 8];
                b_lo[nt][0] = *(const unsigned*)&Bt_lo[n][kb + 2*lr];
                b_lo[nt][1] = *(const unsigned*)&Bt_lo[n][kb + 2*lr + 8];
            }
#pragma unroll
            for (int mt = 0; mt < 2; mt++)
#pragma unroll
                for (int nt = 0; nt < 8; nt++) {
                    mma_bf16(acc[mt][nt], a_hi[mt], b_hi[nt]);
                    mma_bf16(acc[mt][nt], a_lo[mt], b_hi[nt]);
                    mma_bf16(acc[mt][nt], a_hi[mt], b_lo[nt]);
                }
        }
        __syncthreads();
    }

    float pacc[2][2] = {{0.f,0.f},{0.f,0.f}};
#pragma unroll
    for (int nt = 0; nt < 8; nt++) {
        int n0 = warpN*64 + nt*8 + 2*lr;
        float bb0 = __ldg(bias + n0), bb1 = __ldg(bias + n0 + 1);
        float ww0 = __ldg(Ws + n0),   ww1 = __ldg(Ws + n0 + 1);
#pragma unroll
        for (int mt = 0; mt < 2; mt++) {
            int r0 = warpM*32 + mt*16 + lq;
            float v0 = fmaxf(acc[mt][nt][0] + bb0, 0.f);
            float v1 = fmaxf(acc[mt][nt][1] + bb1, 0.f);
            float v2 = fmaxf(acc[mt][nt][2] + bb0, 0.f);
            float v3 = fmaxf(acc[mt][nt][3] + bb1, 0.f);
            *(float2*)(C + (size_t)(row0 + r0)*128 + n0)     = make_float2(v0, v1);
            *(float2*)(C + (size_t)(row0 + r0 + 8)*128 + n0) = make_float2(v2, v3);
            pacc[mt][0] += v0*ww0 + v1*ww1;
            pacc[mt][1] += v2*ww0 + v3*ww1;
        }
    }
#pragma unroll
    for (int mt = 0; mt < 2; mt++)
#pragma unroll
        for (int h = 0; h < 2; h++) {
            float p = pacc[mt][h];
            p += __shfl_xor_sync(0xFFFFFFFFu, p, 1);
            p += __shfl_xor_sync(0xFFFFFFFFu, p, 2);
            if (lr == 0) s0part[warpN][warpM*32 + mt*16 + lq + h*8] = p;
        }
    __syncthreads();
    if (t < 128) s0[row0 + t] = s0part[0][t] + s0part[1][t];
}

// =====================================================================
// k_txr: fused score-GCN + hybrid bitonic top-k + gather*tanh + readout
// =====================================================================
template<int NPG, int ACCUM>
__global__ void k_txr(const int* __restrict__ cnt, const int* __restrict__ off,
                      const unsigned short* __restrict__ csr_src,
                      const float* __restrict__ csr_w,
                      const float* __restrict__ s0, const float* __restrict__ bs,
                      int* __restrict__ newidx,
                      const float* __restrict__ H, float* __restrict__ xnew,
                      float* __restrict__ out) {
    constexpr int K = NPG/2;
    constexpr int G = NPG/128;           // readout row-groups
    __shared__ unsigned long long keys[NPG];
    __shared__ float s_s0l[NPG];
    __shared__ float s_sc [NPG];
    __shared__ int   s_old[K];
    __shared__ float s_t  [K];
    __shared__ float r_mx [NPG];
    __shared__ float r_sm [NPG];
    const int b = blockIdx.x, i = threadIdx.x;
    const int nbase = b*NPG;
    const int gi = nbase + i;

    // ---- score GCN (s0 staged in smem, MLP=4) ----
    s_s0l[i] = s0[gi];
    __syncthreads();
    int c = cnt[gi], o = off[gi];
    float acc = bs[0] + s_s0l[i] / ((float)c + 1.f);
    float acc1 = 0.f, acc2 = 0.f, acc3 = 0.f;
    int j = 0;
    for (; j + 4 <= c; j += 4) {
        int   n0 = csr_src[o+j],   n1 = csr_src[o+j+1];
        int   n2 = csr_src[o+j+2], n3 = csr_src[o+j+3];
        float w0 = csr_w[o+j],   w1 = csr_w[o+j+1];
        float w2 = csr_w[o+j+2], w3 = csr_w[o+j+3];
        acc  += w0 * s_s0l[n0];
        acc1 += w1 * s_s0l[n1];
        acc2 += w2 * s_s0l[n2];
        acc3 += w3 * s_s0l[n3];
    }
    for (; j < c; j++) acc += csr_w[o+j] * s_s0l[csr_src[o+j]];
    acc += acc1 + acc2 + acc3;
    s_sc[i] = acc;
    unsigned u  = __float_as_uint(acc);
    unsigned ou = u ^ ((u & 0x80000000u) ? 0xFFFFFFFFu : 0x80000000u);
    keys[i] = ((unsigned long long)(~ou) << 32) | (unsigned)i;  // asc => desc score, asc idx
    __syncthreads();

    // ---- hybrid bitonic sort: smem steps for j>=32, shfl for j<32 ----
    for (int kk = 2; kk <= NPG; kk <<= 1) {
        for (int js = kk >> 1; js >= 32; js >>= 1) {
            int ixj = i ^ js;
            if (ixj > i) {
                bool up = ((i & kk) == 0);
                unsigned long long a = keys[i], cc2 = keys[ixj];
                if ((a > cc2) == up) { keys[i] = cc2; keys[ixj] = a; }
            }
            __syncthreads();
        }
        {
            unsigned long long v = keys[i];
            const bool up = ((i & kk) == 0);
            int js0 = (kk >> 1) < 16 ? (kk >> 1) : 16;
            for (int js = js0; js > 0; js >>= 1) {
                unsigned long long p = __shfl_xor_sync(0xFFFFFFFFu, v, js);
                bool keepSmall = (((i & js) == 0) == up);
                if ((p < v) == keepSmall) v = p;
            }
            keys[i] = v;
        }
        __syncthreads();
    }

    // ---- topk outputs + newidx ----
    int idx = (int)(keys[i] & 0xFFFFFFFFull);
    if (i < K) {
        s_old[i] = idx;
        s_t[i]   = tanhf(s_sc[idx]);
        newidx[nbase + idx] = b*K + i;
    } else {
        newidx[nbase + idx] = -1;
    }
    __syncthreads();

    // ---- gather*tanh + readout (G row-groups of 128 columns) ----
    const int col = i & 127, g = i >> 7;
    float mx = -3.402823466e38f, sm = 0.f;
    for (int jr = g; jr < K; jr += G) {
        float v = H[(size_t)(nbase + s_old[jr])*128 + col] * s_t[jr];
        xnew[(size_t)(b*K + jr)*128 + col] = v;
        mx = fmaxf(mx, v); sm += v;
    }
    if (G > 1) {
        r_mx[g*128 + col] = mx;
        r_sm[g*128 + col] = sm;
        __syncthreads();
        if (g == 0) {
#pragma unroll
            for (int gg = 1; gg < G; gg++) {
                mx = fmaxf(mx, r_mx[gg*128 + col]);
                sm += r_sm[gg*128 + col];
            }
        }
    }
    if (g == 0) {
        if (ACCUM) {
            out[b*256 + col]       += mx;
            out[b*256 + 128 + col] += sm / (float)K;
        } else {
            out[b*256 + col]       = mx;
            out[b*256 + 128 + col] = sm / (float)K;
        }
    }
}

// =====================================================================
extern "C" void kernel_launch(void* const* d_in, const int* in_sizes, int n_in,
                              void* d_out, int out_size) {
    const float* x   = (const float*)d_in[0];
    const int*   ei  = (const int*)  d_in[1];
    const float* W1  = (const float*)d_in[3];
    const float* b1  = (const float*)d_in[4];
    const float* Ws1 = (const float*)d_in[5];
    const float* bs1 = (const float*)d_in[6];
    const float* W2  = (const float*)d_in[7];
    const float* b2  = (const float*)d_in[8];
    const float* Ws2 = (const float*)d_in[9];
    const float* bs2 = (const float*)d_in[10];
    const float* W3  = (const float*)d_in[11];
    const float* b3  = (const float*)d_in[12];
    const float* Ws3 = (const float*)d_in[13];
    const float* bs3 = (const float*)d_in[14];
    float* out = (float*)d_out;

    __nv_bfloat16 *xah, *xal, *wth, *wtl;
    float *bufB, *bufC, *s0p, *csrw;
    unsigned short *csrs;
    int *srcp, *dstp, *cntp, *offp, *newip;
    cudaGetSymbolAddress((void**)&xah,   g_Xa_hi);
    cudaGetSymbolAddress((void**)&xal,   g_Xa_lo);
    cudaGetSymbolAddress((void**)&wth,   g_Wt_hi);
    cudaGetSymbolAddress((void**)&wtl,   g_Wt_lo);
    cudaGetSymbolAddress((void**)&bufB,  g_bufB);
    cudaGetSymbolAddress((void**)&bufC,  g_bufC);
    cudaGetSymbolAddress((void**)&s0p,   g_s0);
    cudaGetSymbolAddress((void**)&csrw,  g_csr_w);
    cudaGetSymbolAddress((void**)&srcp,  g_src);
    cudaGetSymbolAddress((void**)&dstp,  g_dst);
    cudaGetSymbolAddress((void**)&csrs,  g_csr_src16);
    cudaGetSymbolAddress((void**)&cntp,  g_cnt);
    cudaGetSymbolAddress((void**)&offp,  g_off);
    cudaGetSymbolAddress((void**)&newip, g_newidx);

    const int* ei_src = ei;
    const int* ei_dst = ei + ETOT;

    // ---------------- stage 1: n=512 (shift 9), k=256 ----------------
    {
        const int NT = BGR*512;
        k_prep<512,0,0><<<BGR+1,1024>>>(ei_src, ei_dst, newip, srcp, dstp,
                                        cntp, offp, csrs, csrw, W1, wth, wtl);
        k_agg<<<NT/8,256>>>(x, cntp, offp, csrs, csrw, xah, xal, NT, 9);
        k_gemm_tc<<<NT/128,256>>>(xah, xal, wth, wtl, b1, Ws1, bufB, s0p);
        k_txr<512,0><<<BGR,512>>>(cntp, offp, csrs, csrw, s0p, bs1, newip,
                                  bufB, bufC, out);
    }
    // ---------------- stage 2: n=256 (shift 8), k=128 ----------------
    {
        const int NT = BGR*256;
        k_prep<256,1,1><<<BGR+1,1024>>>(ei_src, ei_dst, newip, srcp, dstp,
                                        cntp, offp, csrs, csrw, W2, wth, wtl);
        k_agg<<<NT/8,256>>>(bufC, cntp, offp, csrs, csrw, xah, xal, NT, 8);
        k_gemm_tc<<<NT/128,256>>>(xah, xal, wth, wtl, b2, Ws2, bufB, s0p);
        k_txr<256,1><<<BGR,256>>>(cntp, offp, csrs, csrw, s0p, bs2, newip,
                                  bufB, bufC, out);
    }
    // ---------------- stage 3: n=128 (shift 7), k=64 ----------------
    {
        const int NT = BGR*128;
        k_prep<128,1,0><<<BGR+1,1024>>>(srcp, dstp, newip, srcp, dstp,
                                        cntp, offp, csrs, csrw, W3, wth, wtl);
        k_agg<<<NT/8,256>>>(bufC, cntp, offp, csrs, csrw, xah, xal, NT, 7);
        k_gemm_tc<<<NT/128,256>>>(xah, xal, wth, wtl, b3, Ws3, bufB, s0p);
        k_txr<128,1><<<BGR,128>>>(cntp, offp, csrs, csrw, s0p, bs3, newip,
                                  bufB, bufC, out);
    }
}

// round 11
// speedup vs baseline: 1.1948x; 1.1948x over previous
#include <cuda_runtime.h>
#include <cuda_bf16.h>
#include <cstdint>

#define BGR   128          // graphs
#define EPG   4096         // edges per graph
#define ETOT  (BGR*EPG)    // 524288 edges
#define FDIM  128
#define NTMAX (BGR*512)    // 65536 max nodes

// ---------------- device scratch ----------------
__device__ __nv_bfloat16 g_Xa_hi[NTMAX*FDIM];   // aggregated input, split bf16
__device__ __nv_bfloat16 g_Xa_lo[NTMAX*FDIM];
__device__ __nv_bfloat16 g_Wt_hi[FDIM*FDIM];    // W transposed [n][k], split bf16
__device__ __nv_bfloat16 g_Wt_lo[FDIM*FDIM];
__device__ float g_bufB[NTMAX*FDIM];   // H  (post-GEMM features)
__device__ float g_bufC[NTMAX*FDIM];   // xnew (next-stage input)
__device__ float g_s0   [NTMAX];
__device__ int   g_src[ETOT];
__device__ int   g_dst[ETOT];
__device__ int   g_csr_src[ETOT];
__device__ float g_csr_w [ETOT];
__device__ int   g_cnt   [NTMAX];
__device__ int   g_off   [NTMAX];
__device__ int   g_newidx[NTMAX];

// =====================================================================
// k_pa: fused per-graph prep (remap+mask+count+dinv+warp-scan+CSR)
//       followed by in-block aggregation Xa -> split bf16 (MLP=4).
// 1024 threads/block; extra block (b == BGR) converts W.
// (This is the measured-best R7 configuration.)
// =====================================================================
template<int NPG, int REMAP, int WRITEBACK>
__global__ __launch_bounds__(1024)
void k_pa(const int* __restrict__ esrc, const int* __restrict__ edst,
          const int* __restrict__ newidx,
          int* __restrict__ osrc, int* __restrict__ odst,
          int* __restrict__ cnt_g, int* __restrict__ off_g,
          int* __restrict__ csr_src_g, float* __restrict__ csr_w_g,
          const float* __restrict__ X,
          __nv_bfloat16* __restrict__ Xa_hi, __nv_bfloat16* __restrict__ Xa_lo,
          const float* __restrict__ W,
          __nv_bfloat16* __restrict__ Wt_hi, __nv_bfloat16* __restrict__ Wt_lo) {
    const int b = blockIdx.x, t = threadIdx.x;
    if (b == BGR) {
        // transpose + split W[128k][128n] -> Wt[n][k]
#pragma unroll
        for (int it = 0; it < 16; it++) {
            int idx = t + it*1024;
            int n = idx >> 7, k = idx & 127;
            float v = W[k*128 + n];
            __nv_bfloat16 h = __float2bfloat16(v);
            Wt_hi[idx] = h;
            Wt_lo[idx] = __float2bfloat16(v - __bfloat162float(h));
        }
        return;
    }
    __shared__ unsigned short s_src[EPG];   // local src per csr slot
    __shared__ float          s_w  [EPG];
    __shared__ int   s_cnt [NPG];
    __shared__ int   s_cur [NPG];
    __shared__ int   s_offl[NPG];
    __shared__ float s_dinv[NPG];
    __shared__ int   s_ws  [NPG/32];        // warp partial sums
    const int ebase = b * EPG;
    const int nbase = b * NPG;
    const int lane = t & 31, wid = t >> 5;
    if (t < NPG) s_cnt[t] = 0;
    __syncthreads();

    int ls[4], ldst[4];
#pragma unroll
    for (int u = 0; u < 4; u++) {
        int e = ebase + u*1024 + t;
        int s = esrc[e], d = edst[e];
        if (REMAP) {
            if (d >= 0) {
                int ns = newidx[s], nd = newidx[d];
                if (ns < 0 || nd < 0) d = -1;
                else { s = ns; d = nd; }
            }
        }
        if (WRITEBACK) { osrc[e] = s; odst[e] = d; }
        if (d >= 0) {
            ls[u]   = s - nbase;
            ldst[u] = d - nbase;
            atomicAdd(&s_cnt[ldst[u]], 1);
        } else ldst[u] = -1;
    }
    __syncthreads();

    // ---- two-level warp-shuffle exclusive scan over NPG counts ----
    int c = 0, vincl = 0;
    if (t < NPG) {
        c = s_cnt[t];
        vincl = c;
#pragma unroll
        for (int d = 1; d < 32; d <<= 1) {
            int nv = __shfl_up_sync(0xFFFFFFFFu, vincl, d);
            if (lane >= d) vincl += nv;
        }
        if (lane == 31) s_ws[wid] = vincl;
        cnt_g[nbase + t] = c;
        s_dinv[t] = rsqrtf((float)c + 1.f);
    }
    __syncthreads();
    if (t < 32) {
        constexpr int NW = NPG/32;
        int v = (t < NW) ? s_ws[t] : 0;
#pragma unroll
        for (int d = 1; d < 32; d <<= 1) {
            int nv = __shfl_up_sync(0xFFFFFFFFu, v, d);
            if (lane >= d) v += nv;
        }
        if (t < NW) s_ws[t] = v;        // inclusive warp-sum prefix
    }
    __syncthreads();
    if (t < NPG) {
        int base = (wid > 0) ? s_ws[wid - 1] : 0;
        int excl = base + vincl - c;
        off_g[nbase + t] = ebase + excl;
        s_offl[t] = excl;
        s_cur[t]  = excl;
    }
    __syncthreads();

#pragma unroll
    for (int u = 0; u < 4; u++) {
        if (ldst[u] >= 0) {
            int pos = atomicAdd(&s_cur[ldst[u]], 1);
            float w = s_dinv[ls[u]] * s_dinv[ldst[u]];
            s_src[pos] = (unsigned short)ls[u];
            s_w  [pos] = w;
            csr_src_g[ebase + pos] = nbase + ls[u];
            csr_w_g  [ebase + pos] = w;
        }
    }
    __syncthreads();

    // ------------- aggregation (32 warps over NPG nodes, MLP=4) -----
    for (int node = wid; node < NPG; node += 32) {
        int cc = s_cnt[node], o = s_offl[node];
        float self = 1.f / ((float)cc + 1.f);
        size_t gi = (size_t)(nbase + node)*128 + lane*4;
        float4 hv = *(const float4*)(X + gi);
        float4 a0 = make_float4(self*hv.x, self*hv.y, self*hv.z, self*hv.w);
        float4 a1 = make_float4(0,0,0,0), a2 = make_float4(0,0,0,0), a3 = make_float4(0,0,0,0);
        int j = 0;
        for (; j + 4 <= cc; j += 4) {
            int   n0 = s_src[o+j],   n1 = s_src[o+j+1];
            int   n2 = s_src[o+j+2], n3 = s_src[o+j+3];
            float w0 = s_w[o+j],   w1 = s_w[o+j+1];
            float w2 = s_w[o+j+2], w3 = s_w[o+j+3];
            float4 h0 = *(const float4*)(X + (size_t)(nbase+n0)*128 + lane*4);
            float4 h1 = *(const float4*)(X + (size_t)(nbase+n1)*128 + lane*4);
            float4 h2 = *(const float4*)(X + (size_t)(nbase+n2)*128 + lane*4);
            float4 h3 = *(const float4*)(X + (size_t)(nbase+n3)*128 + lane*4);
            a0.x += w0*h0.x; a0.y += w0*h0.y; a0.z += w0*h0.z; a0.w += w0*h0.w;
            a1.x += w1*h1.x; a1.y += w1*h1.y; a1.z += w1*h1.z; a1.w += w1*h1.w;
            a2.x += w2*h2.x; a2.y += w2*h2.y; a2.z += w2*h2.z; a2.w += w2*h2.w;
            a3.x += w3*h3.x; a3.y += w3*h3.y; a3.z += w3*h3.z; a3.w += w3*h3.w;
        }
        for (; j < cc; j++) {
            int s = s_src[o+j]; float w = s_w[o+j];
            float4 hs = *(const float4*)(X + (size_t)(nbase+s)*128 + lane*4);
            a0.x += w*hs.x; a0.y += w*hs.y; a0.z += w*hs.z; a0.w += w*hs.w;
        }
        a0.x += a1.x + a2.x + a3.x;
        a0.y += a1.y + a2.y + a3.y;
        a0.z += a1.z + a2.z + a3.z;
        a0.w += a1.w + a2.w + a3.w;
        float f[4] = {a0.x, a0.y, a0.z, a0.w};
        __nv_bfloat16 hi4[4], lo4[4];
#pragma unroll
        for (int e = 0; e < 4; e++) {
            hi4[e] = __float2bfloat16(f[e]);
            lo4[e] = __float2bfloat16(f[e] - __bfloat162float(hi4[e]));
        }
        *(uint2*)(Xa_hi + gi) = *(uint2*)hi4;
        *(uint2*)(Xa_lo + gi) = *(uint2*)lo4;
    }
}

// =====================================================================
// Tensor-core GEMM (split-bf16 operands preconverted; 3 MMA terms):
//   H[M,128] = relu(Xa @ W + b); epilogue also computes s0 = H.Ws
// =====================================================================
__device__ __forceinline__ void mma_bf16(float* d, const unsigned* a, const unsigned* b) {
    asm volatile(
        "mma.sync.aligned.m16n8k16.row.col.f32.bf16.bf16.f32 "
        "{%0,%1,%2,%3}, {%4,%5,%6,%7}, {%8,%9}, {%0,%1,%2,%3};\n"
        : "+f"(d[0]), "+f"(d[1]), "+f"(d[2]), "+f"(d[3])
        : "r"(a[0]), "r"(a[1]), "r"(a[2]), "r"(a[3]), "r"(b[0]), "r"(b[1]));
}

__global__ __launch_bounds__(256)
void k_gemm_tc(const __nv_bfloat16* __restrict__ A_hi,
               const __nv_bfloat16* __restrict__ A_lo,
               const __nv_bfloat16* __restrict__ Wt_hi,
               const __nv_bfloat16* __restrict__ Wt_lo,
               const float* __restrict__ bias, const float* __restrict__ Ws,
               float* __restrict__ C, float* __restrict__ s0) {
    __shared__ __align__(16) __nv_bfloat16 As_hi[128][40];
    __shared__ __align__(16) __nv_bfloat16 As_lo[128][40];
    __shared__ __align__(16) __nv_bfloat16 Bt_hi[128][40];
    __shared__ __align__(16) __nv_bfloat16 Bt_lo[128][40];
    __shared__ float s0part[2][128];

    const int t = threadIdx.x;
    const int warp = t >> 5, lane = t & 31;
    const int warpM = warp >> 1, warpN = warp & 1;
    const int row0 = blockIdx.x * 128;
    const int lq = lane >> 2;
    const int lr = lane & 3;

    float acc[2][8][4];
#pragma unroll
    for (int mt = 0; mt < 2; mt++)
#pragma unroll
        for (int nt = 0; nt < 8; nt++)
#pragma unroll
            for (int r = 0; r < 4; r++) acc[mt][nt][r] = 0.f;

    for (int kc = 0; kc < 4; kc++) {
#pragma unroll
        for (int it = 0; it < 2; it++) {
            int idx = t + it*256;
            int row = idx >> 2;
            int kq  = (idx & 3) * 8;
            size_t ga = (size_t)(row0 + row)*128 + kc*32 + kq;
            *(uint4*)&As_hi[row][kq] = *(const uint4*)(A_hi + ga);
            *(uint4*)&As_lo[row][kq] = *(const uint4*)(A_lo + ga);
            size_t gb = (size_t)row*128 + kc*32 + kq;
            *(uint4*)&Bt_hi[row][kq] = *(const uint4*)(Wt_hi + gb);
            *(uint4*)&Bt_lo[row][kq] = *(const uint4*)(Wt_lo + gb);
        }
        __syncthreads();

#pragma unroll
        for (int ks = 0; ks < 2; ks++) {
            const int kb = ks * 16;
            unsigned a_hi[2][4], a_lo[2][4], b_hi[8][2], b_lo[8][2];
#pragma unroll
            for (int mt = 0; mt < 2; mt++) {
                int m = warpM*32 + mt*16 + lq;
                a_hi[mt][0] = *(const unsigned*)&As_hi[m    ][kb + 2*lr];
                a_hi[mt][1] = *(const unsigned*)&As_hi[m + 8][kb + 2*lr];
                a_hi[mt][2] = *(const unsigned*)&As_hi[m    ][kb + 2*lr + 8];
                a_hi[mt][3] = *(const unsigned*)&As_hi[m + 8][kb + 2*lr + 8];
                a_lo[mt][0] = *(const unsigned*)&As_lo[m    ][kb + 2*lr];
                a_lo[mt][1] = *(const unsigned*)&As_lo[m + 8][kb + 2*lr];
                a_lo[mt][2] = *(const unsigned*)&As_lo[m    ][kb + 2*lr + 8];
                a_lo[mt][3] = *(const unsigned*)&As_lo[m + 8][kb + 2*lr + 8];
            }
#pragma unroll
            for (int nt = 0; nt < 8; nt++) {
                int n = warpN*64 + nt*8 + lq;
                b_hi[nt][0] = *(const unsigned*)&Bt_hi[n][kb + 2*lr];
                b_hi[nt][1] = *(const unsigned*)&Bt_hi[n][kb + 2*lr + 8];
                b_lo[nt][0] = *(const unsigned*)&Bt_lo[n][kb + 2*lr];
                b_lo[nt][1] = *(const unsigned*)&Bt_lo[n][kb + 2*lr + 8];
            }
#pragma unroll
            for (int mt = 0; mt < 2; mt++)
#pragma unroll
                for (int nt = 0; nt < 8; nt++) {
                    mma_bf16(acc[mt][nt], a_hi[mt], b_hi[nt]);
                    mma_bf16(acc[mt][nt], a_lo[mt], b_hi[nt]);
                    mma_bf16(acc[mt][nt], a_hi[mt], b_lo[nt]);
                }
        }
        __syncthreads();
    }

    float pacc[2][2] = {{0.f,0.f},{0.f,0.f}};
#pragma unroll
    for (int nt = 0; nt < 8; nt++) {
        int n0 = warpN*64 + nt*8 + 2*lr;
        float bb0 = __ldg(bias + n0), bb1 = __ldg(bias + n0 + 1);
        float ww0 = __ldg(Ws + n0),   ww1 = __ldg(Ws + n0 + 1);
#pragma unroll
        for (int mt = 0; mt < 2; mt++) {
            int r0 = warpM*32 + mt*16 + lq;
            float v0 = fmaxf(acc[mt][nt][0] + bb0, 0.f);
            float v1 = fmaxf(acc[mt][nt][1] + bb1, 0.f);
            float v2 = fmaxf(acc[mt][nt][2] + bb0, 0.f);
            float v3 = fmaxf(acc[mt][nt][3] + bb1, 0.f);
            *(float2*)(C + (size_t)(row0 + r0)*128 + n0)     = make_float2(v0, v1);
            *(float2*)(C + (size_t)(row0 + r0 + 8)*128 + n0) = make_float2(v2, v3);
            pacc[mt][0] += v0*ww0 + v1*ww1;
            pacc[mt][1] += v2*ww0 + v3*ww1;
        }
    }
#pragma unroll
    for (int mt = 0; mt < 2; mt++)
#pragma unroll
        for (int h = 0; h < 2; h++) {
            float p = pacc[mt][h];
            p += __shfl_xor_sync(0xFFFFFFFFu, p, 1);
            p += __shfl_xor_sync(0xFFFFFFFFu, p, 2);
            if (lr == 0) s0part[warpN][warpM*32 + mt*16 + lq + h*8] = p;
        }
    __syncthreads();
    if (t < 128) s0[row0 + t] = s0part[0][t] + s0part[1][t];
}

// =====================================================================
// k_txr: fused score-GCN + bitonic top-k + gather*tanh + readout.
// Runs with 2*NPG threads: thread pairs split the score gather, the
// readout gets 2x parallelism; sort uses the low NPG threads.
// =====================================================================
template<int NPG, int ACCUM>
__global__ void k_txr(const int* __restrict__ cnt, const int* __restrict__ off,
                      const int* __restrict__ csr_src,
                      const float* __restrict__ csr_w,
                      const float* __restrict__ s0, const float* __restrict__ bs,
                      int* __restrict__ newidx,
                      const float* __restrict__ H, float* __restrict__ xnew,
                      float* __restrict__ out) {
    constexpr int K  = NPG/2;
    constexpr int T2 = 2*NPG;            // block size
    constexpr int G  = T2/128;           // readout row-groups
    __shared__ unsigned long long keys[NPG];
    __shared__ float s_s0l [NPG];
    __shared__ float s_sc  [NPG];
    __shared__ float s_part[NPG];
    __shared__ int   s_old [K];
    __shared__ float s_t   [K];
    __shared__ float r_mx  [T2];
    __shared__ float r_sm  [T2];
    const int b = blockIdx.x, t = threadIdx.x;
    const int nbase = b*NPG;
    const bool lowH = (t < NPG);
    const int node = lowH ? t : t - NPG;

    // ---- stage s0 into smem ----
    if (lowH) s_s0l[t] = s0[nbase + t];
    __syncthreads();

    // ---- score GCN: pair (t, t+NPG) splits node's neighbor list ----
    int c = cnt[nbase + node], o = off[nbase + node];
    int half = c >> 1;
    int jb = lowH ? 0 : half;
    int je = lowH ? half : c;
    float acc = 0.f, acc1 = 0.f, acc2 = 0.f, acc3 = 0.f;
    int j = jb;
    for (; j + 4 <= je; j += 4) {
        int   n0 = csr_src[o+j] - nbase,   n1 = csr_src[o+j+1] - nbase;
        int   n2 = csr_src[o+j+2] - nbase, n3 = csr_src[o+j+3] - nbase;
        float w0 = csr_w[o+j],   w1 = csr_w[o+j+1];
        float w2 = csr_w[o+j+2], w3 = csr_w[o+j+3];
        acc  += w0 * s_s0l[n0];
        acc1 += w1 * s_s0l[n1];
        acc2 += w2 * s_s0l[n2];
        acc3 += w3 * s_s0l[n3];
    }
    for (; j < je; j++) acc += csr_w[o+j] * s_s0l[csr_src[o+j] - nbase];
    acc += acc1 + acc2 + acc3;
    if (!lowH) s_part[node] = acc;
    __syncthreads();
    if (lowH) {
        float total = bs[0] + s_s0l[t] / ((float)c + 1.f) + acc + s_part[t];
        s_sc[t] = total;
        unsigned u  = __float_as_uint(total);
        unsigned ou = u ^ ((u & 0x80000000u) ? 0xFFFFFFFFu : 0x80000000u);
        keys[t] = ((unsigned long long)(~ou) << 32) | (unsigned)t;  // asc => desc score
    }
    __syncthreads();

    // ---- hybrid bitonic sort (low NPG threads; all hit barriers) ----
    for (int kk = 2; kk <= NPG; kk <<= 1) {
        for (int js = kk >> 1; js >= 32; js >>= 1) {
            if (lowH) {
                int ixj = t ^ js;
                if (ixj > t) {
                    bool up = ((t & kk) == 0);
                    unsigned long long a = keys[t], cc2 = keys[ixj];
                    if ((a > cc2) == up) { keys[t] = cc2; keys[ixj] = a; }
                }
            }
            __syncthreads();
        }
        if (lowH) {
            unsigned long long v = keys[t];
            const bool up = ((t & kk) == 0);
            int js0 = (kk >> 1) < 16 ? (kk >> 1) : 16;
            for (int js = js0; js > 0; js >>= 1) {
                unsigned long long p = __shfl_xor_sync(0xFFFFFFFFu, v, js);
                bool keepSmall = (((t & js) == 0) == up);
                if ((p < v) == keepSmall) v = p;
            }
            keys[t] = v;
        }
        __syncthreads();
    }

    // ---- topk outputs + newidx ----
    if (lowH) {
        int idx = (int)(keys[t] & 0xFFFFFFFFull);
        if (t < K) {
            s_old[t] = idx;
            s_t[t]   = tanhf(s_sc[idx]);
            newidx[nbase + idx] = b*K + t;
        } else {
            newidx[nbase + idx] = -1;
        }
    }
    __syncthreads();

    // ---- gather*tanh + readout (G row-groups of 128 columns) ----
    const int col = t & 127, g = t >> 7;
    float mx = -3.402823466e38f, sm = 0.f;
    for (int jr = g; jr < K; jr += G) {
        float v = H[(size_t)(nbase + s_old[jr])*128 + col] * s_t[jr];
        xnew[(size_t)(b*K + jr)*128 + col] = v;
        mx = fmaxf(mx, v); sm += v;
    }
    r_mx[g*128 + col] = mx;
    r_sm[g*128 + col] = sm;
    __syncthreads();
    if (g == 0) {
#pragma unroll
        for (int gg = 1; gg < G; gg++) {
            mx = fmaxf(mx, r_mx[gg*128 + col]);
            sm += r_sm[gg*128 + col];
        }
        if (ACCUM) {
            out[b*256 + col]       += mx;
            out[b*256 + 128 + col] += sm / (float)K;
        } else {
            out[b*256 + col]       = mx;
            out[b*256 + 128 + col] = sm / (float)K;
        }
    }
}

// =====================================================================
extern "C" void kernel_launch(void* const* d_in, const int* in_sizes, int n_in,
                              void* d_out, int out_size) {
    const float* x   = (const float*)d_in[0];
    const int*   ei  = (const int*)  d_in[1];
    const float* W1  = (const float*)d_in[3];
    const float* b1  = (const float*)d_in[4];
    const float* Ws1 = (const float*)d_in[5];
    const float* bs1 = (const float*)d_in[6];
    const float* W2  = (const float*)d_in[7];
    const float* b2  = (const float*)d_in[8];
    const float* Ws2 = (const float*)d_in[9];
    const float* bs2 = (const float*)d_in[10];
    const float* W3  = (const float*)d_in[11];
    const float* b3  = (const float*)d_in[12];
    const float* Ws3 = (const float*)d_in[13];
    const float* bs3 = (const float*)d_in[14];
    float* out = (float*)d_out;

    __nv_bfloat16 *xah, *xal, *wth, *wtl;
    float *bufB, *bufC, *s0p, *csrw;
    int *srcp, *dstp, *csrs, *cntp, *offp, *newip;
    cudaGetSymbolAddress((void**)&xah,   g_Xa_hi);
    cudaGetSymbolAddress((void**)&xal,   g_Xa_lo);
    cudaGetSymbolAddress((void**)&wth,   g_Wt_hi);
    cudaGetSymbolAddress((void**)&wtl,   g_Wt_lo);
    cudaGetSymbolAddress((void**)&bufB,  g_bufB);
    cudaGetSymbolAddress((void**)&bufC,  g_bufC);
    cudaGetSymbolAddress((void**)&s0p,   g_s0);
    cudaGetSymbolAddress((void**)&csrw,  g_csr_w);
    cudaGetSymbolAddress((void**)&srcp,  g_src);
    cudaGetSymbolAddress((void**)&dstp,  g_dst);
    cudaGetSymbolAddress((void**)&csrs,  g_csr_src);
    cudaGetSymbolAddress((void**)&cntp,  g_cnt);
    cudaGetSymbolAddress((void**)&offp,  g_off);
    cudaGetSymbolAddress((void**)&newip, g_newidx);

    const int* ei_src = ei;
    const int* ei_dst = ei + ETOT;

    // ---------------- stage 1: n=512, k=256 ----------------
    {
        const int NT = BGR*512;
        k_pa<512,0,0><<<BGR+1,1024>>>(ei_src, ei_dst, newip, srcp, dstp,
                                      cntp, offp, csrs, csrw,
                                      x, xah, xal, W1, wth, wtl);
        k_gemm_tc<<<NT/128,256>>>(xah, xal, wth, wtl, b1, Ws1, bufB, s0p);
        k_txr<512,0><<<BGR,1024>>>(cntp, offp, csrs, csrw, s0p, bs1, newip,
                                   bufB, bufC, out);
    }
    // ---------------- stage 2: n=256, k=128 ----------------
    {
        const int NT = BGR*256;
        k_pa<256,1,1><<<BGR+1,1024>>>(ei_src, ei_dst, newip, srcp, dstp,
                                      cntp, offp, csrs, csrw,
                                      bufC, xah, xal, W2, wth, wtl);
        k_gemm_tc<<<NT/128,256>>>(xah, xal, wth, wtl, b2, Ws2, bufB, s0p);
        k_txr<256,1><<<BGR,512>>>(cntp, offp, csrs, csrw, s0p, bs2, newip,
                                  bufB, bufC, out);
    }
    // ---------------- stage 3: n=128, k=64 ----------------
    {
        const int NT = BGR*128;
        k_pa<128,1,0><<<BGR+1,1024>>>(srcp, dstp, newip, srcp, dstp,
                                      cntp, offp, csrs, csrw,
                                      bufC, xah, xal, W3, wth, wtl);
        k_gemm_tc<<<NT/128,256>>>(xah, xal, wth, wtl, b3, Ws3, bufB, s0p);
        k_txr<128,1><<<BGR,256>>>(cntp, offp, csrs, csrw, s0p, bs3, newip,
                                  bufB, bufC, out);
    }
}

// round 12
// speedup vs baseline: 1.2723x; 1.0648x over previous
#include <cuda_runtime.h>
#include <cuda_bf16.h>
#include <cstdint>

#define BGR   128          // graphs
#define EPG   4096         // edges per graph
#define ETOT  (BGR*EPG)    // 524288 edges
#define FDIM  128
#define NTMAX (BGR*512)    // 65536 max nodes

// ---------------- device scratch ----------------
__device__ __nv_bfloat16 g_Xa_hi[NTMAX*FDIM];   // aggregated input, split bf16
__device__ __nv_bfloat16 g_Xa_lo[NTMAX*FDIM];
__device__ __nv_bfloat16 g_Wt_hi[FDIM*FDIM];    // W transposed [n][k], split bf16
__device__ __nv_bfloat16 g_Wt_lo[FDIM*FDIM];
__device__ float g_bufB[NTMAX*FDIM];   // H  (post-GEMM features)
__device__ float g_bufC[NTMAX*FDIM];   // xnew (next-stage input)
__device__ float g_s0   [NTMAX];
__device__ int   g_src[ETOT];
__device__ int   g_dst[ETOT];
__device__ int   g_csr_src[ETOT];
__device__ float g_csr_w [ETOT];
__device__ int   g_cntA  [NTMAX];
__device__ int   g_offA  [NTMAX];
__device__ int   g_cntB  [NTMAX];
__device__ int   g_offB  [NTMAX];

// =====================================================================
// k_pa: stage-1 prep (count+dinv+warp-scan+CSR) + in-block aggregation
// (MLP=4). 1024 threads; extra block (b == BGR) converts W1.
// =====================================================================
__global__ __launch_bounds__(1024)
void k_pa1(const int* __restrict__ esrc, const int* __restrict__ edst,
           int* __restrict__ cnt_g, int* __restrict__ off_g,
           int* __restrict__ csr_src_g, float* __restrict__ csr_w_g,
           const float* __restrict__ X,
           __nv_bfloat16* __restrict__ Xa_hi, __nv_bfloat16* __restrict__ Xa_lo,
           const float* __restrict__ W,
           __nv_bfloat16* __restrict__ Wt_hi, __nv_bfloat16* __restrict__ Wt_lo) {
    constexpr int NPG = 512;
    const int b = blockIdx.x, t = threadIdx.x;
    if (b == BGR) {
#pragma unroll
        for (int it = 0; it < 16; it++) {
            int idx = t + it*1024;
            int n = idx >> 7, k = idx & 127;
            float v = W[k*128 + n];
            __nv_bfloat16 h = __float2bfloat16(v);
            Wt_hi[idx] = h;
            Wt_lo[idx] = __float2bfloat16(v - __bfloat162float(h));
        }
        return;
    }
    __shared__ unsigned short s_src[EPG];
    __shared__ float          s_w  [EPG];
    __shared__ int   s_cnt [NPG];
    __shared__ int   s_cur [NPG];
    __shared__ int   s_offl[NPG];
    __shared__ float s_dinv[NPG];
    __shared__ int   s_ws  [NPG/32];
    const int ebase = b * EPG;
    const int nbase = b * NPG;
    const int lane = t & 31, wid = t >> 5;
    if (t < NPG) s_cnt[t] = 0;
    __syncthreads();

    int ls[4], ldst[4];
#pragma unroll
    for (int u = 0; u < 4; u++) {
        int e = ebase + u*1024 + t;
        int s = esrc[e], d = edst[e];
        ls[u]   = s - nbase;
        ldst[u] = d - nbase;
        atomicAdd(&s_cnt[ldst[u]], 1);
    }
    __syncthreads();

    int c = 0, vincl = 0;
    if (t < NPG) {
        c = s_cnt[t];
        vincl = c;
#pragma unroll
        for (int d = 1; d < 32; d <<= 1) {
            int nv = __shfl_up_sync(0xFFFFFFFFu, vincl, d);
            if (lane >= d) vincl += nv;
        }
        if (lane == 31) s_ws[wid] = vincl;
        cnt_g[nbase + t] = c;
        s_dinv[t] = rsqrtf((float)c + 1.f);
    }
    __syncthreads();
    if (t < 32) {
        constexpr int NW = NPG/32;
        int v = (t < NW) ? s_ws[t] : 0;
#pragma unroll
        for (int d = 1; d < 32; d <<= 1) {
            int nv = __shfl_up_sync(0xFFFFFFFFu, v, d);
            if (lane >= d) v += nv;
        }
        if (t < NW) s_ws[t] = v;
    }
    __syncthreads();
    if (t < NPG) {
        int base = (wid > 0) ? s_ws[wid - 1] : 0;
        int excl = base + vincl - c;
        off_g[nbase + t] = ebase + excl;
        s_offl[t] = excl;
        s_cur[t]  = excl;
    }
    __syncthreads();

#pragma unroll
    for (int u = 0; u < 4; u++) {
        int pos = atomicAdd(&s_cur[ldst[u]], 1);
        float w = s_dinv[ls[u]] * s_dinv[ldst[u]];
        s_src[pos] = (unsigned short)ls[u];
        s_w  [pos] = w;
        csr_src_g[ebase + pos] = nbase + ls[u];
        csr_w_g  [ebase + pos] = w;
    }
    __syncthreads();

    for (int node = wid; node < NPG; node += 32) {
        int cc = s_cnt[node], o = s_offl[node];
        float self = 1.f / ((float)cc + 1.f);
        size_t gi = (size_t)(nbase + node)*128 + lane*4;
        float4 hv = *(const float4*)(X + gi);
        float4 a0 = make_float4(self*hv.x, self*hv.y, self*hv.z, self*hv.w);
        float4 a1 = make_float4(0,0,0,0), a2 = make_float4(0,0,0,0), a3 = make_float4(0,0,0,0);
        int j = 0;
        for (; j + 4 <= cc; j += 4) {
            int   n0 = s_src[o+j],   n1 = s_src[o+j+1];
            int   n2 = s_src[o+j+2], n3 = s_src[o+j+3];
            float w0 = s_w[o+j],   w1 = s_w[o+j+1];
            float w2 = s_w[o+j+2], w3 = s_w[o+j+3];
            float4 h0 = *(const float4*)(X + (size_t)(nbase+n0)*128 + lane*4);
            float4 h1 = *(const float4*)(X + (size_t)(nbase+n1)*128 + lane*4);
            float4 h2 = *(const float4*)(X + (size_t)(nbase+n2)*128 + lane*4);
            float4 h3 = *(const float4*)(X + (size_t)(nbase+n3)*128 + lane*4);
            a0.x += w0*h0.x; a0.y += w0*h0.y; a0.z += w0*h0.z; a0.w += w0*h0.w;
            a1.x += w1*h1.x; a1.y += w1*h1.y; a1.z += w1*h1.z; a1.w += w1*h1.w;
            a2.x += w2*h2.x; a2.y += w2*h2.y; a2.z += w2*h2.z; a2.w += w2*h2.w;
            a3.x += w3*h3.x; a3.y += w3*h3.y; a3.z += w3*h3.z; a3.w += w3*h3.w;
        }
        for (; j < cc; j++) {
            int s = s_src[o+j]; float w = s_w[o+j];
            float4 hs = *(const float4*)(X + (size_t)(nbase+s)*128 + lane*4);
            a0.x += w*hs.x; a0.y += w*hs.y; a0.z += w*hs.z; a0.w += w*hs.w;
        }
        a0.x += a1.x + a2.x + a3.x;
        a0.y += a1.y + a2.y + a3.y;
        a0.z += a1.z + a2.z + a3.z;
        a0.w += a1.w + a2.w + a3.w;
        float f[4] = {a0.x, a0.y, a0.z, a0.w};
        __nv_bfloat16 hi4[4], lo4[4];
#pragma unroll
        for (int e = 0; e < 4; e++) {
            hi4[e] = __float2bfloat16(f[e]);
            lo4[e] = __float2bfloat16(f[e] - __bfloat162float(hi4[e]));
        }
        *(uint2*)(Xa_hi + gi) = *(uint2*)hi4;
        *(uint2*)(Xa_lo + gi) = *(uint2*)lo4;
    }
}

// =====================================================================
// Tensor-core GEMM (split-bf16, 3 MMA terms) + fused bias/relu/s0
// =====================================================================
__device__ __forceinline__ void mma_bf16(float* d, const unsigned* a, const unsigned* b) {
    asm volatile(
        "mma.sync.aligned.m16n8k16.row.col.f32.bf16.bf16.f32 "
        "{%0,%1,%2,%3}, {%4,%5,%6,%7}, {%8,%9}, {%0,%1,%2,%3};\n"
        : "+f"(d[0]), "+f"(d[1]), "+f"(d[2]), "+f"(d[3])
        : "r"(a[0]), "r"(a[1]), "r"(a[2]), "r"(a[3]), "r"(b[0]), "r"(b[1]));
}

__global__ __launch_bounds__(256)
void k_gemm_tc(const __nv_bfloat16* __restrict__ A_hi,
               const __nv_bfloat16* __restrict__ A_lo,
               const __nv_bfloat16* __restrict__ Wt_hi,
               const __nv_bfloat16* __restrict__ Wt_lo,
               const float* __restrict__ bias, const float* __restrict__ Ws,
               float* __restrict__ C, float* __restrict__ s0) {
    __shared__ __align__(16) __nv_bfloat16 As_hi[128][40];
    __shared__ __align__(16) __nv_bfloat16 As_lo[128][40];
    __shared__ __align__(16) __nv_bfloat16 Bt_hi[128][40];
    __shared__ __align__(16) __nv_bfloat16 Bt_lo[128][40];
    __shared__ float s0part[2][128];

    const int t = threadIdx.x;
    const int warp = t >> 5, lane = t & 31;
    const int warpM = warp >> 1, warpN = warp & 1;
    const int row0 = blockIdx.x * 128;
    const int lq = lane >> 2;
    const int lr = lane & 3;

    float acc[2][8][4];
#pragma unroll
    for (int mt = 0; mt < 2; mt++)
#pragma unroll
        for (int nt = 0; nt < 8; nt++)
#pragma unroll
            for (int r = 0; r < 4; r++) acc[mt][nt][r] = 0.f;

    for (int kc = 0; kc < 4; kc++) {
#pragma unroll
        for (int it = 0; it < 2; it++) {
            int idx = t + it*256;
            int row = idx >> 2;
            int kq  = (idx & 3) * 8;
            size_t ga = (size_t)(row0 + row)*128 + kc*32 + kq;
            *(uint4*)&As_hi[row][kq] = *(const uint4*)(A_hi + ga);
            *(uint4*)&As_lo[row][kq] = *(const uint4*)(A_lo + ga);
            size_t gb = (size_t)row*128 + kc*32 + kq;
            *(uint4*)&Bt_hi[row][kq] = *(const uint4*)(Wt_hi + gb);
            *(uint4*)&Bt_lo[row][kq] = *(const uint4*)(Wt_lo + gb);
        }
        __syncthreads();

#pragma unroll
        for (int ks = 0; ks < 2; ks++) {
            const int kb = ks * 16;
            unsigned a_hi[2][4], a_lo[2][4], b_hi[8][2], b_lo[8][2];
#pragma unroll
            for (int mt = 0; mt < 2; mt++) {
                int m = warpM*32 + mt*16 + lq;
                a_hi[mt][0] = *(const unsigned*)&As_hi[m    ][kb + 2*lr];
                a_hi[mt][1] = *(const unsigned*)&As_hi[m + 8][kb + 2*lr];
                a_hi[mt][2] = *(const unsigned*)&As_hi[m    ][kb + 2*lr + 8];
                a_hi[mt][3] = *(const unsigned*)&As_hi[m + 8][kb + 2*lr + 8];
                a_lo[mt][0] = *(const unsigned*)&As_lo[m    ][kb + 2*lr];
                a_lo[mt][1] = *(const unsigned*)&As_lo[m + 8][kb + 2*lr];
                a_lo[mt][2] = *(const unsigned*)&As_lo[m    ][kb + 2*lr + 8];
                a_lo[mt][3] = *(const unsigned*)&As_lo[m + 8][kb + 2*lr + 8];
            }
#pragma unroll
            for (int nt = 0; nt < 8; nt++) {
                int n = warpN*64 + nt*8 + lq;
                b_hi[nt][0] = *(const unsigned*)&Bt_hi[n][kb + 2*lr];
                b_hi[nt][1] = *(const unsigned*)&Bt_hi[n][kb + 2*lr + 8];
                b_lo[nt][0] = *(const unsigned*)&Bt_lo[n][kb + 2*lr];
                b_lo[nt][1] = *(const unsigned*)&Bt_lo[n][kb + 2*lr + 8];
            }
#pragma unroll
            for (int mt = 0; mt < 2; mt++)
#pragma unroll
                for (int nt = 0; nt < 8; nt++) {
                    mma_bf16(acc[mt][nt], a_hi[mt], b_hi[nt]);
                    mma_bf16(acc[mt][nt], a_lo[mt], b_hi[nt]);
                    mma_bf16(acc[mt][nt], a_hi[mt], b_lo[nt]);
                }
        }
        __syncthreads();
    }

    float pacc[2][2] = {{0.f,0.f},{0.f,0.f}};
#pragma unroll
    for (int nt = 0; nt < 8; nt++) {
        int n0 = warpN*64 + nt*8 + 2*lr;
        float bb0 = __ldg(bias + n0), bb1 = __ldg(bias + n0 + 1);
        float ww0 = __ldg(Ws + n0),   ww1 = __ldg(Ws + n0 + 1);
#pragma unroll
        for (int mt = 0; mt < 2; mt++) {
            int r0 = warpM*32 + mt*16 + lq;
            float v0 = fmaxf(acc[mt][nt][0] + bb0, 0.f);
            float v1 = fmaxf(acc[mt][nt][1] + bb1, 0.f);
            float v2 = fmaxf(acc[mt][nt][2] + bb0, 0.f);
            float v3 = fmaxf(acc[mt][nt][3] + bb1, 0.f);
            *(float2*)(C + (size_t)(row0 + r0)*128 + n0)     = make_float2(v0, v1);
            *(float2*)(C + (size_t)(row0 + r0 + 8)*128 + n0) = make_float2(v2, v3);
            pacc[mt][0] += v0*ww0 + v1*ww1;
            pacc[mt][1] += v2*ww0 + v3*ww1;
        }
    }
#pragma unroll
    for (int mt = 0; mt < 2; mt++)
#pragma unroll
        for (int h = 0; h < 2; h++) {
            float p = pacc[mt][h];
            p += __shfl_xor_sync(0xFFFFFFFFu, p, 1);
            p += __shfl_xor_sync(0xFFFFFFFFu, p, 2);
            if (lr == 0) s0part[warpN][warpM*32 + mt*16 + lq + h*8] = p;
        }
    __syncthreads();
    if (t < 128) s0[row0 + t] = s0part[0][t] + s0part[1][t];
}

// =====================================================================
// k_txr_pa: FUSED stage-s txr (score+topk+xnew+readout) with
// stage-(s+1) prep+agg, per-graph block (newidx stays in smem).
// 1024 threads; extra block (b == BGR) converts next-stage W.
// =====================================================================
template<int NPGC, int WRITEBACK, int ACCUM>
__global__ __launch_bounds__(1024)
void k_txr_pa(const int* __restrict__ cntC, const int* __restrict__ offC,
              const int* __restrict__ csr_src, const float* __restrict__ csr_w,
              const float* __restrict__ s0, const float* __restrict__ bs,
              const float* __restrict__ H, float* __restrict__ xnew,
              float* __restrict__ out,
              const int* __restrict__ esrc, const int* __restrict__ edst,
              int* __restrict__ osrc, int* __restrict__ odst,
              int* __restrict__ cntN_g, int* __restrict__ offN_g,
              int* __restrict__ csr_src_g, float* __restrict__ csr_w_g,
              __nv_bfloat16* __restrict__ Xa_hi, __nv_bfloat16* __restrict__ Xa_lo,
              const float* __restrict__ W,
              __nv_bfloat16* __restrict__ Wt_hi, __nv_bfloat16* __restrict__ Wt_lo) {
    constexpr int KC   = NPGC/2;     // topk count == next-stage NPG
    constexpr int NPGN = KC;
    const int b = blockIdx.x, t = threadIdx.x;
    if (b == BGR) {
#pragma unroll
        for (int it = 0; it < 16; it++) {
            int idx = t + it*1024;
            int n = idx >> 7, k = idx & 127;
            float v = W[k*128 + n];
            __nv_bfloat16 h = __float2bfloat16(v);
            Wt_hi[idx] = h;
            Wt_lo[idx] = __float2bfloat16(v - __bfloat162float(h));
        }
        return;
    }
    __shared__ union ShU {
        struct {
            unsigned long long keys[NPGC];
            float s0l[NPGC], sc[NPGC], part[NPGC];
            float rmx[2*NPGC], rsm[2*NPGC];
        } x;
        struct {
            unsigned short src[EPG];
            float w[EPG];
            int cnt[NPGN], cur[NPGN], offl[NPGN];
            float dinv[NPGN];
            int ws[NPGN/32];
        } p;
    } sh;
    __shared__ int   s_old[KC];
    __shared__ float s_t  [KC];
    __shared__ int   s_new[NPGC];
    const int nbaseC = b*NPGC, nbaseN = b*NPGN, ebase = b*EPG;
    const int lane = t & 31, wid = t >> 5;
    const bool act  = (t < 2*NPGC);
    const bool lowH = (t < NPGC);

    // ================= PHASE 1: txr (stage s) =================
    if (lowH) sh.x.s0l[t] = s0[nbaseC + t];
    __syncthreads();

    int c = 0;
    float accg = 0.f;
    if (act) {
        const int node = lowH ? t : t - NPGC;
        c = cntC[nbaseC + node];
        int o = offC[nbaseC + node];
        int half = c >> 1;
        int jb = lowH ? 0 : half;
        int je = lowH ? half : c;
        float a1 = 0.f, a2 = 0.f, a3 = 0.f;
        int j = jb;
        for (; j + 4 <= je; j += 4) {
            int   n0 = csr_src[o+j] - nbaseC,   n1 = csr_src[o+j+1] - nbaseC;
            int   n2 = csr_src[o+j+2] - nbaseC, n3 = csr_src[o+j+3] - nbaseC;
            float w0 = csr_w[o+j],   w1 = csr_w[o+j+1];
            float w2 = csr_w[o+j+2], w3 = csr_w[o+j+3];
            accg += w0 * sh.x.s0l[n0];
            a1   += w1 * sh.x.s0l[n1];
            a2   += w2 * sh.x.s0l[n2];
            a3   += w3 * sh.x.s0l[n3];
        }
        for (; j < je; j++) accg += csr_w[o+j] * sh.x.s0l[csr_src[o+j] - nbaseC];
        accg += a1 + a2 + a3;
        if (!lowH) sh.x.part[node] = accg;
    }
    __syncthreads();
    if (lowH) {
        float total = bs[0] + sh.x.s0l[t] / ((float)c + 1.f) + accg + sh.x.part[t];
        sh.x.sc[t] = total;
        unsigned u  = __float_as_uint(total);
        unsigned ou = u ^ ((u & 0x80000000u) ? 0xFFFFFFFFu : 0x80000000u);
        sh.x.keys[t] = ((unsigned long long)(~ou) << 32) | (unsigned)t;
    }
    __syncthreads();

    // hybrid bitonic sort (low NPGC threads; all threads hit barriers)
    for (int kk = 2; kk <= NPGC; kk <<= 1) {
        for (int js = kk >> 1; js >= 32; js >>= 1) {
            if (lowH) {
                int ixj = t ^ js;
                if (ixj > t) {
                    bool up = ((t & kk) == 0);
                    unsigned long long a = sh.x.keys[t], cc2 = sh.x.keys[ixj];
                    if ((a > cc2) == up) { sh.x.keys[t] = cc2; sh.x.keys[ixj] = a; }
                }
            }
            __syncthreads();
        }
        if (lowH) {
            unsigned long long v = sh.x.keys[t];
            const bool up = ((t & kk) == 0);
            int js0 = (kk >> 1) < 16 ? (kk >> 1) : 16;
            for (int js = js0; js > 0; js >>= 1) {
                unsigned long long p = __shfl_xor_sync(0xFFFFFFFFu, v, js);
                bool keepSmall = (((t & js) == 0) == up);
                if ((p < v) == keepSmall) v = p;
            }
            sh.x.keys[t] = v;
        }
        __syncthreads();
    }

    if (lowH) {
        int idx = (int)(sh.x.keys[t] & 0xFFFFFFFFull);
        if (t < KC) {
            s_old[t] = idx;
            s_t[t]   = tanhf(sh.x.sc[idx]);
            s_new[idx] = b*KC + t;
        } else {
            s_new[idx] = -1;
        }
    }
    __syncthreads();

    // gather*tanh + readout
    {
        constexpr int G = (2*NPGC)/128;
        const int col = t & 127, g = t >> 7;
        float mx = -3.402823466e38f, sm = 0.f;
        if (act) {
            for (int jr = g; jr < KC; jr += G) {
                float v = H[(size_t)(nbaseC + s_old[jr])*128 + col] * s_t[jr];
                xnew[(size_t)(b*KC + jr)*128 + col] = v;
                mx = fmaxf(mx, v); sm += v;
            }
            sh.x.rmx[g*128 + col] = mx;
            sh.x.rsm[g*128 + col] = sm;
        }
        __syncthreads();
        if (act && g == 0) {
#pragma unroll
            for (int gg = 1; gg < G; gg++) {
                mx = fmaxf(mx, sh.x.rmx[gg*128 + col]);
                sm += sh.x.rsm[gg*128 + col];
            }
            if (ACCUM) {
                out[b*256 + col]       += mx;
                out[b*256 + 128 + col] += sm / (float)KC;
            } else {
                out[b*256 + col]       = mx;
                out[b*256 + 128 + col] = sm / (float)KC;
            }
        }
    }
    __syncthreads();   // txr smem dead; union flips to prep

    // ================= PHASE 2: prep (stage s+1) =================
    if (t < NPGN) sh.p.cnt[t] = 0;
    __syncthreads();

    int ls[4], ldst[4];
#pragma unroll
    for (int u = 0; u < 4; u++) {
        int e = ebase + u*1024 + t;
        int s = esrc[e], d = edst[e];
        if (d >= 0) {
            int ns = s_new[s - nbaseC], nd = s_new[d - nbaseC];
            if (ns < 0 || nd < 0) d = -1;
            else { s = ns; d = nd; }
        }
        if (WRITEBACK) { osrc[e] = s; odst[e] = d; }
        if (d >= 0) {
            ls[u]   = s - nbaseN;
            ldst[u] = d - nbaseN;
            atomicAdd(&sh.p.cnt[ldst[u]], 1);
        } else ldst[u] = -1;
    }
    __syncthreads();

    int cc = 0, vincl = 0;
    if (t < NPGN) {
        cc = sh.p.cnt[t];
        vincl = cc;
#pragma unroll
        for (int d = 1; d < 32; d <<= 1) {
            int nv = __shfl_up_sync(0xFFFFFFFFu, vincl, d);
            if (lane >= d) vincl += nv;
        }
        if (lane == 31) sh.p.ws[wid] = vincl;
        cntN_g[nbaseN + t] = cc;
        sh.p.dinv[t] = rsqrtf((float)cc + 1.f);
    }
    __syncthreads();
    if (t < 32) {
        constexpr int NW = NPGN/32;
        int v = (t < NW) ? sh.p.ws[t] : 0;
#pragma unroll
        for (int d = 1; d < 32; d <<= 1) {
            int nv = __shfl_up_sync(0xFFFFFFFFu, v, d);
            if (lane >= d) v += nv;
        }
        if (t < NW) sh.p.ws[t] = v;
    }
    __syncthreads();
    if (t < NPGN) {
        int base = (wid > 0) ? sh.p.ws[wid - 1] : 0;
        int excl = base + vincl - cc;
        offN_g[nbaseN + t] = ebase + excl;
        sh.p.offl[t] = excl;
        sh.p.cur[t]  = excl;
    }
    __syncthreads();

#pragma unroll
    for (int u = 0; u < 4; u++) {
        if (ldst[u] >= 0) {
            int pos = atomicAdd(&sh.p.cur[ldst[u]], 1);
            float w = sh.p.dinv[ls[u]] * sh.p.dinv[ldst[u]];
            sh.p.src[pos] = (unsigned short)ls[u];
            sh.p.w  [pos] = w;
            csr_src_g[ebase + pos] = nbaseN + ls[u];
            csr_w_g  [ebase + pos] = w;
        }
    }
    __syncthreads();

    // ================= PHASE 3: agg (stage s+1, MLP=4) =================
    for (int node = wid; node < NPGN; node += 32) {
        int cn = sh.p.cnt[node], o = sh.p.offl[node];
        float self = 1.f / ((float)cn + 1.f);
        size_t gi = (size_t)(nbaseN + node)*128 + lane*4;
        float4 hv = *(const float4*)(xnew + gi);
        float4 a0 = make_float4(self*hv.x, self*hv.y, self*hv.z, self*hv.w);
        float4 a1 = make_float4(0,0,0,0), a2 = make_float4(0,0,0,0), a3 = make_float4(0,0,0,0);
        int j = 0;
        for (; j + 4 <= cn; j += 4) {
            int   n0 = sh.p.src[o+j],   n1 = sh.p.src[o+j+1];
            int   n2 = sh.p.src[o+j+2], n3 = sh.p.src[o+j+3];
            float w0 = sh.p.w[o+j],   w1 = sh.p.w[o+j+1];
            float w2 = sh.p.w[o+j+2], w3 = sh.p.w[o+j+3];
            float4 h0 = *(const float4*)(xnew + (size_t)(nbaseN+n0)*128 + lane*4);
            float4 h1 = *(const float4*)(xnew + (size_t)(nbaseN+n1)*128 + lane*4);
            float4 h2 = *(const float4*)(xnew + (size_t)(nbaseN+n2)*128 + lane*4);
            float4 h3 = *(const float4*)(xnew + (size_t)(nbaseN+n3)*128 + lane*4);
            a0.x += w0*h0.x; a0.y += w0*h0.y; a0.z += w0*h0.z; a0.w += w0*h0.w;
            a1.x += w1*h1.x; a1.y += w1*h1.y; a1.z += w1*h1.z; a1.w += w1*h1.w;
            a2.x += w2*h2.x; a2.y += w2*h2.y; a2.z += w2*h2.z; a2.w += w2*h2.w;
            a3.x += w3*h3.x; a3.y += w3*h3.y; a3.z += w3*h3.z; a3.w += w3*h3.w;
        }
        for (; j < cn; j++) {
            int s = sh.p.src[o+j]; float w = sh.p.w[o+j];
            float4 hs = *(const float4*)(xnew + (size_t)(nbaseN+s)*128 + lane*4);
            a0.x += w*hs.x; a0.y += w*hs.y; a0.z += w*hs.z; a0.w += w*hs.w;
        }
        a0.x += a1.x + a2.x + a3.x;
        a0.y += a1.y + a2.y + a3.y;
        a0.z += a1.z + a2.z + a3.z;
        a0.w += a1.w + a2.w + a3.w;
        float f[4] = {a0.x, a0.y, a0.z, a0.w};
        __nv_bfloat16 hi4[4], lo4[4];
#pragma unroll
        for (int e = 0; e < 4; e++) {
            hi4[e] = __float2bfloat16(f[e]);
            lo4[e] = __float2bfloat16(f[e] - __bfloat162float(hi4[e]));
        }
        *(uint2*)(Xa_hi + gi) = *(uint2*)hi4;
        *(uint2*)(Xa_lo + gi) = *(uint2*)lo4;
    }
}

// =====================================================================
// k_txr: final standalone txr (stage 3) — 2*NPG threads
// =====================================================================
template<int NPG, int ACCUM>
__global__ void k_txr(const int* __restrict__ cnt, const int* __restrict__ off,
                      const int* __restrict__ csr_src,
                      const float* __restrict__ csr_w,
                      const float* __restrict__ s0, const float* __restrict__ bs,
                      const float* __restrict__ H, float* __restrict__ xnew,
                      float* __restrict__ out) {
    constexpr int K  = NPG/2;
    constexpr int T2 = 2*NPG;
    constexpr int G  = T2/128;
    __shared__ unsigned long long keys[NPG];
    __shared__ float s_s0l [NPG];
    __shared__ float s_sc  [NPG];
    __shared__ float s_part[NPG];
    __shared__ int   s_old [K];
    __shared__ float s_t   [K];
    __shared__ float r_mx  [T2];
    __shared__ float r_sm  [T2];
    const int b = blockIdx.x, t = threadIdx.x;
    const int nbase = b*NPG;
    const bool lowH = (t < NPG);
    const int node = lowH ? t : t - NPG;

    if (lowH) s_s0l[t] = s0[nbase + t];
    __syncthreads();

    int c = cnt[nbase + node], o = off[nbase + node];
    int half = c >> 1;
    int jb = lowH ? 0 : half;
    int je = lowH ? half : c;
    float acc = 0.f, acc1 = 0.f, acc2 = 0.f, acc3 = 0.f;
    int j = jb;
    for (; j + 4 <= je; j += 4) {
        int   n0 = csr_src[o+j] - nbase,   n1 = csr_src[o+j+1] - nbase;
        int   n2 = csr_src[o+j+2] - nbase, n3 = csr_src[o+j+3] - nbase;
        float w0 = csr_w[o+j],   w1 = csr_w[o+j+1];
        float w2 = csr_w[o+j+2], w3 = csr_w[o+j+3];
        acc  += w0 * s_s0l[n0];
        acc1 += w1 * s_s0l[n1];
        acc2 += w2 * s_s0l[n2];
        acc3 += w3 * s_s0l[n3];
    }
    for (; j < je; j++) acc += csr_w[o+j] * s_s0l[csr_src[o+j] - nbase];
    acc += acc1 + acc2 + acc3;
    if (!lowH) s_part[node] = acc;
    __syncthreads();
    if (lowH) {
        float total = bs[0] + s_s0l[t] / ((float)c + 1.f) + acc + s_part[t];
        s_sc[t] = total;
        unsigned u  = __float_as_uint(total);
        unsigned ou = u ^ ((u & 0x80000000u) ? 0xFFFFFFFFu : 0x80000000u);
        keys[t] = ((unsigned long long)(~ou) << 32) | (unsigned)t;
    }
    __syncthreads();

    for (int kk = 2; kk <= NPG; kk <<= 1) {
        for (int js = kk >> 1; js >= 32; js >>= 1) {
            if (lowH) {
                int ixj = t ^ js;
                if (ixj > t) {
                    bool up = ((t & kk) == 0);
                    unsigned long long a = keys[t], cc2 = keys[ixj];
                    if ((a > cc2) == up) { keys[t] = cc2; keys[ixj] = a; }
                }
            }
            __syncthreads();
        }
        if (lowH) {
            unsigned long long v = keys[t];
            const bool up = ((t & kk) == 0);
            int js0 = (kk >> 1) < 16 ? (kk >> 1) : 16;
            for (int js = js0; js > 0; js >>= 1) {
                unsigned long long p = __shfl_xor_sync(0xFFFFFFFFu, v, js);
                bool keepSmall = (((t & js) == 0) == up);
                if ((p < v) == keepSmall) v = p;
            }
            keys[t] = v;
        }
        __syncthreads();
    }

    if (lowH && t < K) {
        int idx = (int)(keys[t] & 0xFFFFFFFFull);
        s_old[t] = idx;
        s_t[t]   = tanhf(s_sc[idx]);
    }
    __syncthreads();

    const int col = t & 127, g = t >> 7;
    float mx = -3.402823466e38f, sm = 0.f;
    for (int jr = g; jr < K; jr += G) {
        float v = H[(size_t)(nbase + s_old[jr])*128 + col] * s_t[jr];
        xnew[(size_t)(b*K + jr)*128 + col] = v;
        mx = fmaxf(mx, v); sm += v;
    }
    r_mx[g*128 + col] = mx;
    r_sm[g*128 + col] = sm;
    __syncthreads();
    if (g == 0) {
#pragma unroll
        for (int gg = 1; gg < G; gg++) {
            mx = fmaxf(mx, r_mx[gg*128 + col]);
            sm += r_sm[gg*128 + col];
        }
        if (ACCUM) {
            out[b*256 + col]       += mx;
            out[b*256 + 128 + col] += sm / (float)K;
        } else {
            out[b*256 + col]       = mx;
            out[b*256 + 128 + col] = sm / (float)K;
        }
    }
}

// =====================================================================
extern "C" void kernel_launch(void* const* d_in, const int* in_sizes, int n_in,
                              void* d_out, int out_size) {
    const float* x   = (const float*)d_in[0];
    const int*   ei  = (const int*)  d_in[1];
    const float* W1  = (const float*)d_in[3];
    const float* b1  = (const float*)d_in[4];
    const float* Ws1 = (const float*)d_in[5];
    const float* bs1 = (const float*)d_in[6];
    const float* W2  = (const float*)d_in[7];
    const float* b2  = (const float*)d_in[8];
    const float* Ws2 = (const float*)d_in[9];
    const float* bs2 = (const float*)d_in[10];
    const float* W3  = (const float*)d_in[11];
    const float* b3  = (const float*)d_in[12];
    const float* Ws3 = (const float*)d_in[13];
    const float* bs3 = (const float*)d_in[14];
    float* out = (float*)d_out;

    __nv_bfloat16 *xah, *xal, *wth, *wtl;
    float *bufB, *bufC, *s0p, *csrw;
    int *srcp, *dstp, *csrs, *cntA, *offA, *cntB, *offB;
    cudaGetSymbolAddress((void**)&xah,  g_Xa_hi);
    cudaGetSymbolAddress((void**)&xal,  g_Xa_lo);
    cudaGetSymbolAddress((void**)&wth,  g_Wt_hi);
    cudaGetSymbolAddress((void**)&wtl,  g_Wt_lo);
    cudaGetSymbolAddress((void**)&bufB, g_bufB);
    cudaGetSymbolAddress((void**)&bufC, g_bufC);
    cudaGetSymbolAddress((void**)&s0p,  g_s0);
    cudaGetSymbolAddress((void**)&csrw, g_csr_w);
    cudaGetSymbolAddress((void**)&srcp, g_src);
    cudaGetSymbolAddress((void**)&dstp, g_dst);
    cudaGetSymbolAddress((void**)&csrs, g_csr_src);
    cudaGetSymbolAddress((void**)&cntA, g_cntA);
    cudaGetSymbolAddress((void**)&offA, g_offA);
    cudaGetSymbolAddress((void**)&cntB, g_cntB);
    cudaGetSymbolAddress((void**)&offB, g_offB);

    const int* ei_src = ei;
    const int* ei_dst = ei + ETOT;

    // stage 1 prep+agg (writes cntA/offA, csr, Xa) + W1 conversion
    k_pa1<<<BGR+1,1024>>>(ei_src, ei_dst, cntA, offA, csrs, csrw,
                          x, xah, xal, W1, wth, wtl);
    // stage 1 GEMM
    k_gemm_tc<<<BGR*512/128,256>>>(xah, xal, wth, wtl, b1, Ws1, bufB, s0p);
    // txr1 + prep2 + agg2 (reads cntA; writes cntB, csr, Xa; W2 conv)
    k_txr_pa<512,1,0><<<BGR+1,1024>>>(cntA, offA, csrs, csrw, s0p, bs1,
                                      bufB, bufC, out,
                                      ei_src, ei_dst, srcp, dstp,
                                      cntB, offB, csrs, csrw,
                                      xah, xal, W2, wth, wtl);
    // stage 2 GEMM
    k_gemm_tc<<<BGR*256/128,256>>>(xah, xal, wth, wtl, b2, Ws2, bufB, s0p);
    // txr2 + prep3 + agg3 (reads cntB; writes cntA, csr, Xa; W3 conv)
    k_txr_pa<256,0,1><<<BGR+1,1024>>>(cntB, offB, csrs, csrw, s0p, bs2,
                                      bufB, bufC, out,
                                      srcp, dstp, srcp, dstp,
                                      cntA, offA, csrs, csrw,
                                      xah, xal, W3, wth, wtl);
    // stage 3 GEMM
    k_gemm_tc<<<BGR*128/128,256>>>(xah, xal, wth, wtl, b3, Ws3, bufB, s0p);
    // final txr (stage 3)
    k_txr<128,1><<<BGR,256>>>(cntA, offA, csrs, csrw, s0p, bs3,
                              bufB, bufC, out);
}

// round 15
// speedup vs baseline: 1.2961x; 1.0187x over previous
#include <cuda_runtime.h>
#include <cuda_bf16.h>
#include <cstdint>

#define BGR   128          // graphs
#define EPG   4096         // edges per graph
#define ETOT  (BGR*EPG)    // 524288 edges
#define FDIM  128
#define NTMAX (BGR*512)    // 65536 max nodes

// ---------------- device scratch ----------------
__device__ __nv_bfloat16 g_Xa_hi[NTMAX*FDIM];   // aggregated input, split bf16
__device__ __nv_bfloat16 g_Xa_lo[NTMAX*FDIM];
__device__ __nv_bfloat16 g_Wt_hi[FDIM*FDIM];    // W transposed [n][k], split bf16
__device__ __nv_bfloat16 g_Wt_lo[FDIM*FDIM];
__device__ float g_bufB[NTMAX*FDIM];   // H  (post-GEMM features)
__device__ float g_bufC[NTMAX*FDIM];   // xnew (next-stage input)
__device__ float g_s0   [NTMAX];
__device__ int   g_src[ETOT];
__device__ int   g_dst[ETOT];
__device__ int   g_csr_src[ETOT];
__device__ float g_csr_w [ETOT];
__device__ int   g_cntA  [NTMAX];
__device__ int   g_offA  [NTMAX];
__device__ int   g_cntB  [NTMAX];
__device__ int   g_offB  [NTMAX];

// =====================================================================
// k_pa1: stage-1 prep + in-block aggregation (MLP=4). 1024 threads;
// extra block (b == BGR) converts W1.
// =====================================================================
__global__ __launch_bounds__(1024)
void k_pa1(const int* __restrict__ esrc, const int* __restrict__ edst,
           int* __restrict__ cnt_g, int* __restrict__ off_g,
           int* __restrict__ csr_src_g, float* __restrict__ csr_w_g,
           const float* __restrict__ X,
           __nv_bfloat16* __restrict__ Xa_hi, __nv_bfloat16* __restrict__ Xa_lo,
           const float* __restrict__ W,
           __nv_bfloat16* __restrict__ Wt_hi, __nv_bfloat16* __restrict__ Wt_lo) {
    constexpr int NPG = 512;
    const int b = blockIdx.x, t = threadIdx.x;
    if (b == BGR) {
#pragma unroll
        for (int it = 0; it < 16; it++) {
            int idx = t + it*1024;
            int n = idx >> 7, k = idx & 127;
            float v = W[k*128 + n];
            __nv_bfloat16 h = __float2bfloat16(v);
            Wt_hi[idx] = h;
            Wt_lo[idx] = __float2bfloat16(v - __bfloat162float(h));
        }
        return;
    }
    __shared__ unsigned short s_src[EPG];
    __shared__ float          s_w  [EPG];
    __shared__ int   s_cnt [NPG];
    __shared__ int   s_cur [NPG];
    __shared__ int   s_offl[NPG];
    __shared__ float s_dinv[NPG];
    __shared__ int   s_ws  [NPG/32];
    const int ebase = b * EPG;
    const int nbase = b * NPG;
    const int lane = t & 31, wid = t >> 5;
    if (t < NPG) s_cnt[t] = 0;
    __syncthreads();

    int ls[4], ldst[4];
#pragma unroll
    for (int u = 0; u < 4; u++) {
        int e = ebase + u*1024 + t;
        int s = esrc[e], d = edst[e];
        ls[u]   = s - nbase;
        ldst[u] = d - nbase;
        atomicAdd(&s_cnt[ldst[u]], 1);
    }
    __syncthreads();

    int c = 0, vincl = 0;
    if (t < NPG) {
        c = s_cnt[t];
        vincl = c;
#pragma unroll
        for (int d = 1; d < 32; d <<= 1) {
            int nv = __shfl_up_sync(0xFFFFFFFFu, vincl, d);
            if (lane >= d) vincl += nv;
        }
        if (lane == 31) s_ws[wid] = vincl;
        cnt_g[nbase + t] = c;
        s_dinv[t] = rsqrtf((float)c + 1.f);
    }
    __syncthreads();
    if (t < 32) {
        constexpr int NW = NPG/32;
        int v = (t < NW) ? s_ws[t] : 0;
#pragma unroll
        for (int d = 1; d < 32; d <<= 1) {
            int nv = __shfl_up_sync(0xFFFFFFFFu, v, d);
            if (lane >= d) v += nv;
        }
        if (t < NW) s_ws[t] = v;
    }
    __syncthreads();
    if (t < NPG) {
        int base = (wid > 0) ? s_ws[wid - 1] : 0;
        int excl = base + vincl - c;
        off_g[nbase + t] = ebase + excl;
        s_offl[t] = excl;
        s_cur[t]  = excl;
    }
    __syncthreads();

#pragma unroll
    for (int u = 0; u < 4; u++) {
        int pos = atomicAdd(&s_cur[ldst[u]], 1);
        float w = s_dinv[ls[u]] * s_dinv[ldst[u]];
        s_src[pos] = (unsigned short)ls[u];
        s_w  [pos] = w;
        csr_src_g[ebase + pos] = nbase + ls[u];
        csr_w_g  [ebase + pos] = w;
    }
    __syncthreads();

    for (int node = wid; node < NPG; node += 32) {
        int cc = s_cnt[node], o = s_offl[node];
        float self = 1.f / ((float)cc + 1.f);
        size_t gi = (size_t)(nbase + node)*128 + lane*4;
        float4 hv = *(const float4*)(X + gi);
        float4 a0 = make_float4(self*hv.x, self*hv.y, self*hv.z, self*hv.w);
        float4 a1 = make_float4(0,0,0,0), a2 = make_float4(0,0,0,0), a3 = make_float4(0,0,0,0);
        int j = 0;
        for (; j + 4 <= cc; j += 4) {
            int   n0 = s_src[o+j],   n1 = s_src[o+j+1];
            int   n2 = s_src[o+j+2], n3 = s_src[o+j+3];
            float w0 = s_w[o+j],   w1 = s_w[o+j+1];
            float w2 = s_w[o+j+2], w3 = s_w[o+j+3];
            float4 h0 = *(const float4*)(X + (size_t)(nbase+n0)*128 + lane*4);
            float4 h1 = *(const float4*)(X + (size_t)(nbase+n1)*128 + lane*4);
            float4 h2 = *(const float4*)(X + (size_t)(nbase+n2)*128 + lane*4);
            float4 h3 = *(const float4*)(X + (size_t)(nbase+n3)*128 + lane*4);
            a0.x += w0*h0.x; a0.y += w0*h0.y; a0.z += w0*h0.z; a0.w += w0*h0.w;
            a1.x += w1*h1.x; a1.y += w1*h1.y; a1.z += w1*h1.z; a1.w += w1*h1.w;
            a2.x += w2*h2.x; a2.y += w2*h2.y; a2.z += w2*h2.z; a2.w += w2*h2.w;
            a3.x += w3*h3.x; a3.y += w3*h3.y; a3.z += w3*h3.z; a3.w += w3*h3.w;
        }
        for (; j < cc; j++) {
            int s = s_src[o+j]; float w = s_w[o+j];
            float4 hs = *(const float4*)(X + (size_t)(nbase+s)*128 + lane*4);
            a0.x += w*hs.x; a0.y += w*hs.y; a0.z += w*hs.z; a0.w += w*hs.w;
        }
        a0.x += a1.x + a2.x + a3.x;
        a0.y += a1.y + a2.y + a3.y;
        a0.z += a1.z + a2.z + a3.z;
        a0.w += a1.w + a2.w + a3.w;
        float f[4] = {a0.x, a0.y, a0.z, a0.w};
        __nv_bfloat16 hi4[4], lo4[4];
#pragma unroll
        for (int e = 0; e < 4; e++) {
            hi4[e] = __float2bfloat16(f[e]);
            lo4[e] = __float2bfloat16(f[e] - __bfloat162float(hi4[e]));
        }
        *(uint2*)(Xa_hi + gi) = *(uint2*)hi4;
        *(uint2*)(Xa_lo + gi) = *(uint2*)lo4;
    }
}

// =====================================================================
// Tensor-core GEMM: uint4 smem fill (proven) + ldmatrix fragment loads.
//   H[M,128] = relu(Xa @ W + b); epilogue computes s0 = H.Ws
// =====================================================================
__device__ __forceinline__ void mma_bf16(float* d, const unsigned* a, const unsigned* b) {
    asm volatile(
        "mma.sync.aligned.m16n8k16.row.col.f32.bf16.bf16.f32 "
        "{%0,%1,%2,%3}, {%4,%5,%6,%7}, {%8,%9}, {%0,%1,%2,%3};\n"
        : "+f"(d[0]), "+f"(d[1]), "+f"(d[2]), "+f"(d[3])
        : "r"(a[0]), "r"(a[1]), "r"(a[2]), "r"(a[3]), "r"(b[0]), "r"(b[1]));
}
__device__ __forceinline__ void ldsm4(unsigned* r, uint32_t a) {
    asm volatile("ldmatrix.sync.aligned.m8n8.x4.shared.b16 {%0,%1,%2,%3}, [%4];\n"
        : "=r"(r[0]), "=r"(r[1]), "=r"(r[2]), "=r"(r[3]) : "r"(a));
}

__global__ __launch_bounds__(256)
void k_gemm_tc(const __nv_bfloat16* __restrict__ A_hi,
               const __nv_bfloat16* __restrict__ A_lo,
               const __nv_bfloat16* __restrict__ Wt_hi,
               const __nv_bfloat16* __restrict__ Wt_lo,
               const float* __restrict__ bias, const float* __restrict__ Ws,
               float* __restrict__ C, float* __restrict__ s0) {
    __shared__ __align__(16) __nv_bfloat16 As_hi[128][40];
    __shared__ __align__(16) __nv_bfloat16 As_lo[128][40];
    __shared__ __align__(16) __nv_bfloat16 Bt_hi[128][40];
    __shared__ __align__(16) __nv_bfloat16 Bt_lo[128][40];
    __shared__ float s0part[2][128];

    const int t = threadIdx.x;
    const int warp = t >> 5, lane = t & 31;
    const int warpM = warp >> 1, warpN = warp & 1;
    const int row0 = blockIdx.x * 128;
    const int lq = lane >> 2;
    const int lr = lane & 3;

    const uint32_t sAhi = (uint32_t)__cvta_generic_to_shared(&As_hi[0][0]);
    const uint32_t sAlo = (uint32_t)__cvta_generic_to_shared(&As_lo[0][0]);
    const uint32_t sBhi = (uint32_t)__cvta_generic_to_shared(&Bt_hi[0][0]);
    const uint32_t sBlo = (uint32_t)__cvta_generic_to_shared(&Bt_lo[0][0]);

    // ldmatrix per-thread source addresses (byte offsets)
    const int aOff = ((warpM*32 + (lane & 7) + ((lane >> 3) & 1)*8) * 40
                      + (lane >> 4)*8) * 2;
    const int bOff = ((warpN*64 + (lane & 7) + (lane >> 4)*8) * 40
                      + ((lane >> 3) & 1)*8) * 2;

    float acc[2][8][4];
#pragma unroll
    for (int mt = 0; mt < 2; mt++)
#pragma unroll
        for (int nt = 0; nt < 8; nt++)
#pragma unroll
            for (int r = 0; r < 4; r++) acc[mt][nt][r] = 0.f;

    for (int kc = 0; kc < 4; kc++) {
        // ---- proven uint4 smem fill (R12) ----
#pragma unroll
        for (int it = 0; it < 2; it++) {
            int idx = t + it*256;
            int row = idx >> 2;
            int kq  = (idx & 3) * 8;
            size_t ga = (size_t)(row0 + row)*128 + kc*32 + kq;
            *(uint4*)&As_hi[row][kq] = *(const uint4*)(A_hi + ga);
            *(uint4*)&As_lo[row][kq] = *(const uint4*)(A_lo + ga);
            size_t gb = (size_t)row*128 + kc*32 + kq;
            *(uint4*)&Bt_hi[row][kq] = *(const uint4*)(Wt_hi + gb);
            *(uint4*)&Bt_lo[row][kq] = *(const uint4*)(Wt_lo + gb);
        }
        __syncthreads();

#pragma unroll
        for (int ks = 0; ks < 2; ks++) {
            const int kb2 = ks * 32;          // 16 cols * 2 bytes
            unsigned a_hi[2][4], a_lo[2][4];
            ldsm4(a_hi[0], sAhi + aOff + kb2);
            ldsm4(a_hi[1], sAhi + aOff + 1280 + kb2);   // +16 rows * 80B
            ldsm4(a_lo[0], sAlo + aOff + kb2);
            ldsm4(a_lo[1], sAlo + aOff + 1280 + kb2);
#pragma unroll
            for (int ntp = 0; ntp < 4; ntp++) {
                unsigned bh[4], bl[4];
                ldsm4(bh, sBhi + bOff + ntp*1280 + kb2);
                ldsm4(bl, sBlo + bOff + ntp*1280 + kb2);
#pragma unroll
                for (int mt = 0; mt < 2; mt++) {
                    mma_bf16(acc[mt][2*ntp],   a_hi[mt], bh);
                    mma_bf16(acc[mt][2*ntp],   a_lo[mt], bh);
                    mma_bf16(acc[mt][2*ntp],   a_hi[mt], bl);
                    mma_bf16(acc[mt][2*ntp+1], a_hi[mt], bh + 2);
                    mma_bf16(acc[mt][2*ntp+1], a_lo[mt], bh + 2);
                    mma_bf16(acc[mt][2*ntp+1], a_hi[mt], bl + 2);
                }
            }
        }
        __syncthreads();
    }

    float pacc[2][2] = {{0.f,0.f},{0.f,0.f}};
#pragma unroll
    for (int nt = 0; nt < 8; nt++) {
        int n0 = warpN*64 + nt*8 + 2*lr;
        float bb0 = __ldg(bias + n0), bb1 = __ldg(bias + n0 + 1);
        float ww0 = __ldg(Ws + n0),   ww1 = __ldg(Ws + n0 + 1);
#pragma unroll
        for (int mt = 0; mt < 2; mt++) {
            int r0 = warpM*32 + mt*16 + lq;
            float v0 = fmaxf(acc[mt][nt][0] + bb0, 0.f);
            float v1 = fmaxf(acc[mt][nt][1] + bb1, 0.f);
            float v2 = fmaxf(acc[mt][nt][2] + bb0, 0.f);
            float v3 = fmaxf(acc[mt][nt][3] + bb1, 0.f);
            *(float2*)(C + (size_t)(row0 + r0)*128 + n0)     = make_float2(v0, v1);
            *(float2*)(C + (size_t)(row0 + r0 + 8)*128 + n0) = make_float2(v2, v3);
            pacc[mt][0] += v0*ww0 + v1*ww1;
            pacc[mt][1] += v2*ww0 + v3*ww1;
        }
    }
#pragma unroll
    for (int mt = 0; mt < 2; mt++)
#pragma unroll
        for (int h = 0; h < 2; h++) {
            float p = pacc[mt][h];
            p += __shfl_xor_sync(0xFFFFFFFFu, p, 1);
            p += __shfl_xor_sync(0xFFFFFFFFu, p, 2);
            if (lr == 0) s0part[warpN][warpM*32 + mt*16 + lq + h*8] = p;
        }
    __syncthreads();
    if (t < 128) s0[row0 + t] = s0part[0][t] + s0part[1][t];
}

// =====================================================================
// k_txr_pa: FUSED stage-s txr with stage-(s+1) prep+agg (per-graph).
// =====================================================================
template<int NPGC, int WRITEBACK, int ACCUM>
__global__ __launch_bounds__(1024)
void k_txr_pa(const int* __restrict__ cntC, const int* __restrict__ offC,
              const int* __restrict__ csr_src, const float* __restrict__ csr_w,
              const float* __restrict__ s0, const float* __restrict__ bs,
              const float* __restrict__ H, float* __restrict__ xnew,
              float* __restrict__ out,
              const int* __restrict__ esrc, const int* __restrict__ edst,
              int* __restrict__ osrc, int* __restrict__ odst,
              int* __restrict__ cntN_g, int* __restrict__ offN_g,
              int* __restrict__ csr_src_g, float* __restrict__ csr_w_g,
              __nv_bfloat16* __restrict__ Xa_hi, __nv_bfloat16* __restrict__ Xa_lo,
              const float* __restrict__ W,
              __nv_bfloat16* __restrict__ Wt_hi, __nv_bfloat16* __restrict__ Wt_lo) {
    constexpr int KC   = NPGC/2;
    constexpr int NPGN = KC;
    const int b = blockIdx.x, t = threadIdx.x;
    if (b == BGR) {
#pragma unroll
        for (int it = 0; it < 16; it++) {
            int idx = t + it*1024;
            int n = idx >> 7, k = idx & 127;
            float v = W[k*128 + n];
            __nv_bfloat16 h = __float2bfloat16(v);
            Wt_hi[idx] = h;
            Wt_lo[idx] = __float2bfloat16(v - __bfloat162float(h));
        }
        return;
    }
    __shared__ union ShU {
        struct {
            unsigned long long keys[NPGC];
            float s0l[NPGC], sc[NPGC], part[NPGC];
            float rmx[2*NPGC], rsm[2*NPGC];
        } x;
        struct {
            unsigned short src[EPG];
            float w[EPG];
            int cnt[NPGN], cur[NPGN], offl[NPGN];
            float dinv[NPGN];
            int ws[NPGN/32];
        } p;
    } sh;
    __shared__ int   s_old[KC];
    __shared__ float s_t  [KC];
    __shared__ int   s_new[NPGC];
    const int nbaseC = b*NPGC, nbaseN = b*NPGN, ebase = b*EPG;
    const int lane = t & 31, wid = t >> 5;
    const bool act  = (t < 2*NPGC);
    const bool lowH = (t < NPGC);

    // ================= PHASE 1: txr (stage s) =================
    if (lowH) sh.x.s0l[t] = s0[nbaseC + t];
    __syncthreads();

    int c = 0;
    float accg = 0.f;
    if (act) {
        const int node = lowH ? t : t - NPGC;
        c = cntC[nbaseC + node];
        int o = offC[nbaseC + node];
        int half = c >> 1;
        int jb = lowH ? 0 : half;
        int je = lowH ? half : c;
        float a1 = 0.f, a2 = 0.f, a3 = 0.f;
        int j = jb;
        for (; j + 4 <= je; j += 4) {
            int   n0 = csr_src[o+j] - nbaseC,   n1 = csr_src[o+j+1] - nbaseC;
            int   n2 = csr_src[o+j+2] - nbaseC, n3 = csr_src[o+j+3] - nbaseC;
            float w0 = csr_w[o+j],   w1 = csr_w[o+j+1];
            float w2 = csr_w[o+j+2], w3 = csr_w[o+j+3];
            accg += w0 * sh.x.s0l[n0];
            a1   += w1 * sh.x.s0l[n1];
            a2   += w2 * sh.x.s0l[n2];
            a3   += w3 * sh.x.s0l[n3];
        }
        for (; j < je; j++) accg += csr_w[o+j] * sh.x.s0l[csr_src[o+j] - nbaseC];
        accg += a1 + a2 + a3;
        if (!lowH) sh.x.part[node] = accg;
    }
    __syncthreads();
    if (lowH) {
        float total = bs[0] + sh.x.s0l[t] / ((float)c + 1.f) + accg + sh.x.part[t];
        sh.x.sc[t] = total;
        unsigned u  = __float_as_uint(total);
        unsigned ou = u ^ ((u & 0x80000000u) ? 0xFFFFFFFFu : 0x80000000u);
        sh.x.keys[t] = ((unsigned long long)(~ou) << 32) | (unsigned)t;
    }
    __syncthreads();

    for (int kk = 2; kk <= NPGC; kk <<= 1) {
        for (int js = kk >> 1; js >= 32; js >>= 1) {
            if (lowH) {
                int ixj = t ^ js;
                if (ixj > t) {
                    bool up = ((t & kk) == 0);
                    unsigned long long a = sh.x.keys[t], cc2 = sh.x.keys[ixj];
                    if ((a > cc2) == up) { sh.x.keys[t] = cc2; sh.x.keys[ixj] = a; }
                }
            }
            __syncthreads();
        }
        if (lowH) {
            unsigned long long v = sh.x.keys[t];
            const bool up = ((t & kk) == 0);
            int js0 = (kk >> 1) < 16 ? (kk >> 1) : 16;
            for (int js = js0; js > 0; js >>= 1) {
                unsigned long long p = __shfl_xor_sync(0xFFFFFFFFu, v, js);
                bool keepSmall = (((t & js) == 0) == up);
                if ((p < v) == keepSmall) v = p;
            }
            sh.x.keys[t] = v;
        }
        __syncthreads();
    }

    if (lowH) {
        int idx = (int)(sh.x.keys[t] & 0xFFFFFFFFull);
        if (t < KC) {
            s_old[t] = idx;
            s_t[t]   = tanhf(sh.x.sc[idx]);
            s_new[idx] = b*KC + t;
        } else {
            s_new[idx] = -1;
        }
    }
    __syncthreads();

    {
        constexpr int G = (2*NPGC)/128;
        const int col = t & 127, g = t >> 7;
        float mx = -3.402823466e38f, sm = 0.f;
        if (act) {
            for (int jr = g; jr < KC; jr += G) {
                float v = H[(size_t)(nbaseC + s_old[jr])*128 + col] * s_t[jr];
                xnew[(size_t)(b*KC + jr)*128 + col] = v;
                mx = fmaxf(mx, v); sm += v;
            }
            sh.x.rmx[g*128 + col] = mx;
            sh.x.rsm[g*128 + col] = sm;
        }
        __syncthreads();
        if (act && g == 0) {
#pragma unroll
            for (int gg = 1; gg < G; gg++) {
                mx = fmaxf(mx, sh.x.rmx[gg*128 + col]);
                sm += sh.x.rsm[gg*128 + col];
            }
            if (ACCUM) {
                out[b*256 + col]       += mx;
                out[b*256 + 128 + col] += sm / (float)KC;
            } else {
                out[b*256 + col]       = mx;
                out[b*256 + 128 + col] = sm / (float)KC;
            }
        }
    }
    __syncthreads();

    // ================= PHASE 2: prep (stage s+1) =================
    if (t < NPGN) sh.p.cnt[t] = 0;
    __syncthreads();

    int ls[4], ldst[4];
#pragma unroll
    for (int u = 0; u < 4; u++) {
        int e = ebase + u*1024 + t;
        int s = esrc[e], d = edst[e];
        if (d >= 0) {
            int ns = s_new[s - nbaseC], nd = s_new[d - nbaseC];
            if (ns < 0 || nd < 0) d = -1;
            else { s = ns; d = nd; }
        }
        if (WRITEBACK) { osrc[e] = s; odst[e] = d; }
        if (d >= 0) {
            ls[u]   = s - nbaseN;
            ldst[u] = d - nbaseN;
            atomicAdd(&sh.p.cnt[ldst[u]], 1);
        } else ldst[u] = -1;
    }
    __syncthreads();

    int cc = 0, vincl = 0;
    if (t < NPGN) {
        cc = sh.p.cnt[t];
        vincl = cc;
#pragma unroll
        for (int d = 1; d < 32; d <<= 1) {
            int nv = __shfl_up_sync(0xFFFFFFFFu, vincl, d);
            if (lane >= d) vincl += nv;
        }
        if (lane == 31) sh.p.ws[wid] = vincl;
        cntN_g[nbaseN + t] = cc;
        sh.p.dinv[t] = rsqrtf((float)cc + 1.f);
    }
    __syncthreads();
    if (t < 32) {
        constexpr int NW = NPGN/32;
        int v = (t < NW) ? sh.p.ws[t] : 0;
#pragma unroll
        for (int d = 1; d < 32; d <<= 1) {
            int nv = __shfl_up_sync(0xFFFFFFFFu, v, d);
            if (lane >= d) v += nv;
        }
        if (t < NW) sh.p.ws[t] = v;
    }
    __syncthreads();
    if (t < NPGN) {
        int base = (wid > 0) ? sh.p.ws[wid - 1] : 0;
        int excl = base + vincl - cc;
        offN_g[nbaseN + t] = ebase + excl;
        sh.p.offl[t] = excl;
        sh.p.cur[t]  = excl;
    }
    __syncthreads();

#pragma unroll
    for (int u = 0; u < 4; u++) {
        if (ldst[u] >= 0) {
            int pos = atomicAdd(&sh.p.cur[ldst[u]], 1);
            float w = sh.p.dinv[ls[u]] * sh.p.dinv[ldst[u]];
            sh.p.src[pos] = (unsigned short)ls[u];
            sh.p.w  [pos] = w;
            csr_src_g[ebase + pos] = nbaseN + ls[u];
            csr_w_g  [ebase + pos] = w;
        }
    }
    __syncthreads();

    // ================= PHASE 3: agg (stage s+1, MLP=4) =================
    for (int node = wid; node < NPGN; node += 32) {
        int cn = sh.p.cnt[node], o = sh.p.offl[node];
        float self = 1.f / ((float)cn + 1.f);
        size_t gi = (size_t)(nbaseN + node)*128 + lane*4;
        float4 hv = *(const float4*)(xnew + gi);
        float4 a0 = make_float4(self*hv.x, self*hv.y, self*hv.z, self*hv.w);
        float4 a1 = make_float4(0,0,0,0), a2 = make_float4(0,0,0,0), a3 = make_float4(0,0,0,0);
        int j = 0;
        for (; j + 4 <= cn; j += 4) {
            int   n0 = sh.p.src[o+j],   n1 = sh.p.src[o+j+1];
            int   n2 = sh.p.src[o+j+2], n3 = sh.p.src[o+j+3];
            float w0 = sh.p.w[o+j],   w1 = sh.p.w[o+j+1];
            float w2 = sh.p.w[o+j+2], w3 = sh.p.w[o+j+3];
            float4 h0 = *(const float4*)(xnew + (size_t)(nbaseN+n0)*128 + lane*4);
            float4 h1 = *(const float4*)(xnew + (size_t)(nbaseN+n1)*128 + lane*4);
            float4 h2 = *(const float4*)(xnew + (size_t)(nbaseN+n2)*128 + lane*4);
            float4 h3 = *(const float4*)(xnew + (size_t)(nbaseN+n3)*128 + lane*4);
            a0.x += w0*h0.x; a0.y += w0*h0.y; a0.z += w0*h0.z; a0.w += w0*h0.w;
            a1.x += w1*h1.x; a1.y += w1*h1.y; a1.z += w1*h1.z; a1.w += w1*h1.w;
            a2.x += w2*h2.x; a2.y += w2*h2.y; a2.z += w2*h2.z; a2.w += w2*h2.w;
            a3.x += w3*h3.x; a3.y += w3*h3.y; a3.z += w3*h3.z; a3.w += w3*h3.w;
        }
        for (; j < cn; j++) {
            int s = sh.p.src[o+j]; float w = sh.p.w[o+j];
            float4 hs = *(const float4*)(xnew + (size_t)(nbaseN+s)*128 + lane*4);
            a0.x += w*hs.x; a0.y += w*hs.y; a0.z += w*hs.z; a0.w += w*hs.w;
        }
        a0.x += a1.x + a2.x + a3.x;
        a0.y += a1.y + a2.y + a3.y;
        a0.z += a1.z + a2.z + a3.z;
        a0.w += a1.w + a2.w + a3.w;
        float f[4] = {a0.x, a0.y, a0.z, a0.w};
        __nv_bfloat16 hi4[4], lo4[4];
#pragma unroll
        for (int e = 0; e < 4; e++) {
            hi4[e] = __float2bfloat16(f[e]);
            lo4[e] = __float2bfloat16(f[e] - __bfloat162float(hi4[e]));
        }
        *(uint2*)(Xa_hi + gi) = *(uint2*)hi4;
        *(uint2*)(Xa_lo + gi) = *(uint2*)lo4;
    }
}

// =====================================================================
// k_txr: final standalone txr (stage 3) — 2*NPG threads
// =====================================================================
template<int NPG, int ACCUM>
__global__ void k_txr(const int* __restrict__ cnt, const int* __restrict__ off,
                      const int* __restrict__ csr_src,
                      const float* __restrict__ csr_w,
                      const float* __restrict__ s0, const float* __restrict__ bs,
                      const float* __restrict__ H, float* __restrict__ xnew,
                      float* __restrict__ out) {
    constexpr int K  = NPG/2;
    constexpr int T2 = 2*NPG;
    constexpr int G  = T2/128;
    __shared__ unsigned long long keys[NPG];
    __shared__ float s_s0l [NPG];
    __shared__ float s_sc  [NPG];
    __shared__ float s_part[NPG];
    __shared__ int   s_old [K];
    __shared__ float s_t   [K];
    __shared__ float r_mx  [T2];
    __shared__ float r_sm  [T2];
    const int b = blockIdx.x, t = threadIdx.x;
    const int nbase = b*NPG;
    const bool lowH = (t < NPG);
    const int node = lowH ? t : t - NPG;

    if (lowH) s_s0l[t] = s0[nbase + t];
    __syncthreads();

    int c = cnt[nbase + node], o = off[nbase + node];
    int half = c >> 1;
    int jb = lowH ? 0 : half;
    int je = lowH ? half : c;
    float acc = 0.f, acc1 = 0.f, acc2 = 0.f, acc3 = 0.f;
    int j = jb;
    for (; j + 4 <= je; j += 4) {
        int   n0 = csr_src[o+j] - nbase,   n1 = csr_src[o+j+1] - nbase;
        int   n2 = csr_src[o+j+2] - nbase, n3 = csr_src[o+j+3] - nbase;
        float w0 = csr_w[o+j],   w1 = csr_w[o+j+1];
        float w2 = csr_w[o+j+2], w3 = csr_w[o+j+3];
        acc  += w0 * s_s0l[n0];
        acc1 += w1 * s_s0l[n1];
        acc2 += w2 * s_s0l[n2];
        acc3 += w3 * s_s0l[n3];
    }
    for (; j < je; j++) acc += csr_w[o+j] * s_s0l[csr_src[o+j] - nbase];
    acc += acc1 + acc2 + acc3;
    if (!lowH) s_part[node] = acc;
    __syncthreads();
    if (lowH) {
        float total = bs[0] + s_s0l[t] / ((float)c + 1.f) + acc + s_part[t];
        s_sc[t] = total;
        unsigned u  = __float_as_uint(total);
        unsigned ou = u ^ ((u & 0x80000000u) ? 0xFFFFFFFFu : 0x80000000u);
        keys[t] = ((unsigned long long)(~ou) << 32) | (unsigned)t;
    }
    __syncthreads();

    for (int kk = 2; kk <= NPG; kk <<= 1) {
        for (int js = kk >> 1; js >= 32; js >>= 1) {
            if (lowH) {
                int ixj = t ^ js;
                if (ixj > t) {
                    bool up = ((t & kk) == 0);
                    unsigned long long a = keys[t], cc2 = keys[ixj];
                    if ((a > cc2) == up) { keys[t] = cc2; keys[ixj] = a; }
                }
            }
            __syncthreads();
        }
        if (lowH) {
            unsigned long long v = keys[t];
            const bool up = ((t & kk) == 0);
            int js0 = (kk >> 1) < 16 ? (kk >> 1) : 16;
            for (int js = js0; js > 0; js >>= 1) {
                unsigned long long p = __shfl_xor_sync(0xFFFFFFFFu, v, js);
                bool keepSmall = (((t & js) == 0) == up);
                if ((p < v) == keepSmall) v = p;
            }
            keys[t] = v;
        }
        __syncthreads();
    }

    if (lowH && t < K) {
        int idx = (int)(keys[t] & 0xFFFFFFFFull);
        s_old[t] = idx;
        s_t[t]   = tanhf(s_sc[idx]);
    }
    __syncthreads();

    const int col = t & 127, g = t >> 7;
    float mx = -3.402823466e38f, sm = 0.f;
    for (int jr = g; jr < K; jr += G) {
        float v = H[(size_t)(nbase + s_old[jr])*128 + col] * s_t[jr];
        xnew[(size_t)(b*K + jr)*128 + col] = v;
        mx = fmaxf(mx, v); sm += v;
    }
    r_mx[g*128 + col] = mx;
    r_sm[g*128 + col] = sm;
    __syncthreads();
    if (g == 0) {
#pragma unroll
        for (int gg = 1; gg < G; gg++) {
            mx = fmaxf(mx, r_mx[gg*128 + col]);
            sm += r_sm[gg*128 + col];
        }
        if (ACCUM) {
            out[b*256 + col]       += mx;
            out[b*256 + 128 + col] += sm / (float)K;
        } else {
            out[b*256 + col]       = mx;
            out[b*256 + 128 + col] = sm / (float)K;
        }
    }
}

// =====================================================================
extern "C" void kernel_launch(void* const* d_in, const int* in_sizes, int n_in,
                              void* d_out, int out_size) {
    const float* x   = (const float*)d_in[0];
    const int*   ei  = (const int*)  d_in[1];
    const float* W1  = (const float*)d_in[3];
    const float* b1  = (const float*)d_in[4];
    const float* Ws1 = (const float*)d_in[5];
    const float* bs1 = (const float*)d_in[6];
    const float* W2  = (const float*)d_in[7];
    const float* b2  = (const float*)d_in[8];
    const float* Ws2 = (const float*)d_in[9];
    const float* bs2 = (const float*)d_in[10];
    const float* W3  = (const float*)d_in[11];
    const float* b3  = (const float*)d_in[12];
    const float* Ws3 = (const float*)d_in[13];
    const float* bs3 = (const float*)d_in[14];
    float* out = (float*)d_out;

    __nv_bfloat16 *xah, *xal, *wth, *wtl;
    float *bufB, *bufC, *s0p, *csrw;
    int *srcp, *dstp, *csrs, *cntA, *offA, *cntB, *offB;
    cudaGetSymbolAddress((void**)&xah,  g_Xa_hi);
    cudaGetSymbolAddress((void**)&xal,  g_Xa_lo);
    cudaGetSymbolAddress((void**)&wth,  g_Wt_hi);
    cudaGetSymbolAddress((void**)&wtl,  g_Wt_lo);
    cudaGetSymbolAddress((void**)&bufB, g_bufB);
    cudaGetSymbolAddress((void**)&bufC, g_bufC);
    cudaGetSymbolAddress((void**)&s0p,  g_s0);
    cudaGetSymbolAddress((void**)&csrw, g_csr_w);
    cudaGetSymbolAddress((void**)&srcp, g_src);
    cudaGetSymbolAddress((void**)&dstp, g_dst);
    cudaGetSymbolAddress((void**)&csrs, g_csr_src);
    cudaGetSymbolAddress((void**)&cntA, g_cntA);
    cudaGetSymbolAddress((void**)&offA, g_offA);
    cudaGetSymbolAddress((void**)&cntB, g_cntB);
    cudaGetSymbolAddress((void**)&offB, g_offB);

    const int* ei_src = ei;
    const int* ei_dst = ei + ETOT;

    k_pa1<<<BGR+1,1024>>>(ei_src, ei_dst, cntA, offA, csrs, csrw,
                          x, xah, xal, W1, wth, wtl);
    k_gemm_tc<<<BGR*512/128,256>>>(xah, xal, wth, wtl, b1, Ws1, bufB, s0p);
    k_txr_pa<512,1,0><<<BGR+1,1024>>>(cntA, offA, csrs, csrw, s0p, bs1,
                                      bufB, bufC, out,
                                      ei_src, ei_dst, srcp, dstp,
                                      cntB, offB, csrs, csrw,
                                      xah, xal, W2, wth, wtl);
    k_gemm_tc<<<BGR*256/128,256>>>(xah, xal, wth, wtl, b2, Ws2, bufB, s0p);
    k_txr_pa<256,0,1><<<BGR+1,1024>>>(cntB, offB, csrs, csrw, s0p, bs2,
                                      bufB, bufC, out,
                                      srcp, dstp, srcp, dstp,
                                      cntA, offA, csrs, csrw,
                                      xah, xal, W3, wth, wtl);
    k_gemm_tc<<<BGR*128/128,256>>>(xah, xal, wth, wtl, b3, Ws3, bufB, s0p);
    k_txr<128,1><<<BGR,256>>>(cntA, offA, csrs, csrw, s0p, bs3,
                              bufB, bufC, out);
}